// round 2
// baseline (speedup 1.0000x reference)
#include <cuda_runtime.h>

#define BSZ 1024
#define GF 512
#define IFT 512
#define OFT 512
#define NL 64
#define GC 63
#define KMAIN (IFT * NL)      // 32768
#define KTOT (KMAIN + NL)     // 32832 (pb folded in as extra K columns)

#define BM 64
#define BN 64
#define BK 16
#define TM 4
#define TN 4
#define NTHREADS 256

// scratch for leaf probabilities [B, NL]
__device__ float g_leafp[BSZ * NL];

// ---------------------------------------------------------------------------
// Kernel 1: gating GEMV + sigmoid + tree product -> leaf_probs [1024, 64]
// ---------------------------------------------------------------------------
__global__ void leaf_probs_kernel(const float* __restrict__ xg,
                                  const float* __restrict__ gw,
                                  const float* __restrict__ gb) {
    __shared__ float xs[GF];
    __shared__ float sg[GC];
    const int b = blockIdx.x;
    const int tid = threadIdx.x;

    for (int f = tid; f < GF; f += 128) xs[f] = xg[b * GF + f];
    __syncthreads();

    if (tid < GC) {
        float a0 = 0.f, a1 = 0.f, a2 = 0.f, a3 = 0.f;
        #pragma unroll 4
        for (int f = 0; f < GF; f += 4) {
            a0 += xs[f + 0] * gw[(f + 0) * GC + tid];
            a1 += xs[f + 1] * gw[(f + 1) * GC + tid];
            a2 += xs[f + 2] * gw[(f + 2) * GC + tid];
            a3 += xs[f + 3] * gw[(f + 3) * GC + tid];
        }
        float z = (a0 + a1) + (a2 + a3) + gb[tid];
        sg[tid] = 1.f / (1.f + expf(-z));
    }
    __syncthreads();

    if (tid < NL) {
        const int l = tid;
        float p = 1.f;
        #pragma unroll
        for (int d = 0; d < 6; d++) {
            int node = l >> (6 - d);              // parent index at depth d
            int idx  = (1 << d) - 1 + node;       // gate index
            int bit  = (l >> (5 - d)) & 1;        // 0 -> g, 1 -> (1-g)
            float g = sg[idx];
            p *= bit ? (1.f - g) : g;
        }
        g_leafp[b * NL + l] = p;
    }
}

// ---------------------------------------------------------------------------
// Kernel 2: C[1024,512] = A[1024,32832] @ B[512,32832]^T
//   A[b, i*64+l] = x_leaf[b,i] * p[b,l]   (generated in SMEM, never in HBM)
//   A[b, 32768+l] = p[b,l]
//   B[o, k]      = pw[o*32768 + k]  ;  B[o, 32768+l] = pb[o*64 + l]
// ---------------------------------------------------------------------------
__global__ __launch_bounds__(NTHREADS, 1) void hme_gemm_kernel(
    const float* __restrict__ xleaf,
    const float* __restrict__ pw,
    const float* __restrict__ pb,
    float* __restrict__ out) {

    __shared__ float p_s[BM][NL + 1];     // leaf probs for this M-block (pad: bank shift)
    __shared__ float xcol[BM];            // x_leaf column i0 for this M-block
    __shared__ float As[BK][BM + 4];      // A tile, k-major rows (pad keeps 16B align)
    __shared__ float Bs[BK][BN + 4];      // B tile

    const int tid = threadIdx.x;
    const int tx = tid & 15;              // N direction (16 * TN = 64)
    const int ty = tid >> 4;              // M direction (16 * TM = 64)
    const int m0 = blockIdx.y * BM;
    const int n0 = blockIdx.x * BN;

    // stage leaf probs for the whole block once
    for (int idx = tid; idx < BM * NL; idx += NTHREADS) {
        int m = idx >> 6, l = idx & 63;
        p_s[m][l] = g_leafp[(m0 + m) * NL + l];
    }

    float acc[TM][TN];
    #pragma unroll
    for (int i = 0; i < TM; i++)
        #pragma unroll
        for (int j = 0; j < TN; j++) acc[i][j] = 0.f;

    const int bn = tid >> 2;              // 0..63 : output row within B tile
    const int bq = tid & 3;               // 0..3  : k quad

    for (int k0 = 0; k0 < KTOT; k0 += BK) {
        const bool main_part = (k0 < KMAIN);
        const int i0 = k0 >> 6;           // x_leaf feature index (fixed per tile)
        const int l0 = k0 & 63;           // leaf offset (BK=16 divides 64)

        // refresh x column every 4 tiles (i0 changes). Safe: previous As-gen
        // (the only xcol reader) completed before last tile's 2nd barrier.
        if (main_part && l0 == 0 && tid < BM)
            xcol[tid] = xleaf[(size_t)(m0 + tid) * IFT + i0];

        // global load of B tile into registers (pw or pb region)
        float4 bv;
        if (main_part) {
            bv = *reinterpret_cast<const float4*>(
                pw + (size_t)(n0 + bn) * KMAIN + k0 + bq * 4);
        } else {
            bv = *reinterpret_cast<const float4*>(
                pb + (n0 + bn) * NL + (k0 - KMAIN) + bq * 4);
        }

        __syncthreads();   // (1) prev inner loop done; xcol visible

        Bs[bq * 4 + 0][bn] = bv.x;
        Bs[bq * 4 + 1][bn] = bv.y;
        Bs[bq * 4 + 2][bn] = bv.z;
        Bs[bq * 4 + 3][bn] = bv.w;

        // generate A tile: As[k][m] = x[m,i0] * p[m, l0+k]  (x := 1 in pb region)
        #pragma unroll
        for (int r = 0; r < 4; r++) {
            int e = tid + r * NTHREADS;   // 0..1023
            int kk = e >> 6;              // 0..15
            int m = e & 63;
            float xv = main_part ? xcol[m] : 1.f;
            As[kk][m] = xv * p_s[m][l0 + kk];
        }

        __syncthreads();   // (2) tiles ready

        #pragma unroll
        for (int k = 0; k < BK; k++) {
            float4 av = *reinterpret_cast<const float4*>(&As[k][ty * TM]);
            float4 bw = *reinterpret_cast<const float4*>(&Bs[k][tx * TN]);
            float a[TM] = {av.x, av.y, av.z, av.w};
            float bb[TN] = {bw.x, bw.y, bw.z, bw.w};
            #pragma unroll
            for (int i = 0; i < TM; i++)
                #pragma unroll
                for (int j = 0; j < TN; j++)
                    acc[i][j] += a[i] * bb[j];
        }
    }

    // epilogue: coalesced float4 stores
    #pragma unroll
    for (int i = 0; i < TM; i++) {
        int m = m0 + ty * TM + i;
        float4 o4 = make_float4(acc[i][0], acc[i][1], acc[i][2], acc[i][3]);
        *reinterpret_cast<float4*>(out + (size_t)m * OFT + n0 + tx * TN) = o4;
    }
}

// ---------------------------------------------------------------------------
extern "C" void kernel_launch(void* const* d_in, const int* in_sizes, int n_in,
                              void* d_out, int out_size) {
    const float* xg = (const float*)d_in[0];  // x_gating [1024,512]
    const float* xl = (const float*)d_in[1];  // x_leaf   [1024,512]
    const float* gw = (const float*)d_in[2];  // [512,63]
    const float* gb = (const float*)d_in[3];  // [63]
    const float* pw = (const float*)d_in[4];  // [512,512,64]
    const float* pb = (const float*)d_in[5];  // [512,64]
    float* out = (float*)d_out;               // [1024,512] f32

    leaf_probs_kernel<<<BSZ, 128>>>(xg, gw, gb);

    dim3 grid(OFT / BN, BSZ / BM);            // (8, 16) = 128 CTAs
    hme_gemm_kernel<<<grid, NTHREADS>>>(xl, pw, pb, out);
}

// round 4
// speedup vs baseline: 3.6954x; 3.6954x over previous
#include <cuda_runtime.h>
#include <cuda_bf16.h>
#include <cstdint>

#define BSZ 1024
#define GF 512
#define IFT 512
#define OFT 512
#define NL 64
#define GC 63
#define KMAIN (IFT * NL)          // 32768
#define KSPLIT 4
#define TILE_M 128
#define TILE_N 128
#define NTHR 256

// ---------------------------------------------------------------------------
// static device scratch
// ---------------------------------------------------------------------------
__device__ __align__(256) float g_leafp[BSZ * NL];                  // 256KB
__device__ __align__(256) float g_xT[IFT * BSZ];                    // 2MB
__device__ __align__(256) float g_part[(size_t)KSPLIT * BSZ * OFT]; // 8MB

// ---------------------------------------------------------------------------
// smem layout (dynamic): 2 bf16 tile-sets + 2 fp32 stages + 2 x-columns
// ---------------------------------------------------------------------------
#define ROWB 144                    // bf16 tile row stride (64*2 + 16 pad)
#define TILEB (128 * ROWB)          // 18432
#define SETSZ (4 * TILEB)           // AHI|ALO|BHI|BLO = 73728
#define OFF_AHI 0
#define OFF_ALO TILEB
#define OFF_BHI (2 * TILEB)
#define OFF_BLO (3 * TILEB)
#define STGROW 272                  // fp32 stage row stride (64*4 + 16 pad)
#define STGSZ (128 * STGROW)        // 34816
#define OFF_STG0 (2 * SETSZ)        // 147456
#define OFF_STG1 (OFF_STG0 + STGSZ) // 182272
#define OFF_X0   (OFF_STG1 + STGSZ) // 217088
#define OFF_X1   (OFF_X0 + 512)
#define SMEM_SZ  (OFF_X1 + 512)     // 218112

// ---------------------------------------------------------------------------
// PTX helpers (base sm_103 target only: no 'a'-gated instructions!)
// ---------------------------------------------------------------------------
__device__ __forceinline__ uint32_t smem_u32(const void* p) {
    uint32_t a;
    asm("{ .reg .u64 t; cvta.to.shared.u64 t, %1; cvt.u32.u64 %0, t; }" : "=r"(a) : "l"(p));
    return a;
}
#define CPA16(dst, src) \
    asm volatile("cp.async.cg.shared.global [%0], [%1], 16;" :: "r"(dst), "l"(src) : "memory")
#define CPCOMMIT() asm volatile("cp.async.commit_group;" ::: "memory")
#define CPWAIT1()  asm volatile("cp.async.wait_group 1;" ::: "memory")

__device__ __forceinline__ void ldsm4(uint32_t (&r)[4], uint32_t a) {
    asm volatile("ldmatrix.sync.aligned.m8n8.x4.shared.b16 {%0,%1,%2,%3}, [%4];"
        : "=r"(r[0]), "=r"(r[1]), "=r"(r[2]), "=r"(r[3]) : "r"(a));
}
__device__ __forceinline__ void mma16816(float* d, const uint32_t* a, const uint32_t* b) {
    asm volatile("mma.sync.aligned.m16n8k16.row.col.f32.bf16.bf16.f32 "
        "{%0,%1,%2,%3}, {%4,%5,%6,%7}, {%8,%9}, {%0,%1,%2,%3};"
        : "+f"(d[0]), "+f"(d[1]), "+f"(d[2]), "+f"(d[3])
        : "r"(a[0]), "r"(a[1]), "r"(a[2]), "r"(a[3]), "r"(b[0]), "r"(b[1]));
}
__device__ __forceinline__ uint32_t bits2(__nv_bfloat162 h) {
    return *reinterpret_cast<uint32_t*>(&h);
}

// ---------------------------------------------------------------------------
// Kernel 1: gating GEMV + sigmoid + tree product -> g_leafp
// ---------------------------------------------------------------------------
__global__ void leaf_probs_kernel(const float* __restrict__ xg,
                                  const float* __restrict__ gw,
                                  const float* __restrict__ gb) {
    __shared__ float xs[GF];
    __shared__ float sg[GC];
    const int b = blockIdx.x;
    const int tid = threadIdx.x;
    for (int f = tid; f < GF; f += 128) xs[f] = xg[b * GF + f];
    __syncthreads();
    if (tid < GC) {
        float a0 = 0.f, a1 = 0.f, a2 = 0.f, a3 = 0.f;
        #pragma unroll 4
        for (int f = 0; f < GF; f += 4) {
            a0 += xs[f + 0] * gw[(f + 0) * GC + tid];
            a1 += xs[f + 1] * gw[(f + 1) * GC + tid];
            a2 += xs[f + 2] * gw[(f + 2) * GC + tid];
            a3 += xs[f + 3] * gw[(f + 3) * GC + tid];
        }
        float z = (a0 + a1) + (a2 + a3) + gb[tid];
        sg[tid] = 1.f / (1.f + expf(-z));
    }
    __syncthreads();
    if (tid < NL) {
        const int l = tid;
        float p = 1.f;
        #pragma unroll
        for (int d = 0; d < 6; d++) {
            int node = l >> (6 - d);
            int idx  = (1 << d) - 1 + node;
            int bit  = (l >> (5 - d)) & 1;
            float g = sg[idx];
            p *= bit ? (1.f - g) : g;
        }
        g_leafp[b * NL + l] = p;
    }
}

// ---------------------------------------------------------------------------
// Kernel 2: transpose x_leaf [B, IFT] -> g_xT [IFT, B]
// ---------------------------------------------------------------------------
__global__ void transpose_kernel(const float* __restrict__ x) {
    __shared__ float t[32][33];
    int i0 = blockIdx.x * 32, b0 = blockIdx.y * 32;
    for (int r = threadIdx.y; r < 32; r += 8)
        t[r][threadIdx.x] = x[(size_t)(b0 + r) * IFT + i0 + threadIdx.x];
    __syncthreads();
    for (int r = threadIdx.y; r < 32; r += 8)
        g_xT[(size_t)(i0 + r) * BSZ + b0 + threadIdx.x] = t[threadIdx.x][r];
}

// ---------------------------------------------------------------------------
// Main GEMM: mma.sync bf16 3-term split, cp.async 3-stage pipeline
// ---------------------------------------------------------------------------
__device__ __forceinline__ void issue_stage(uint32_t sb, int buf, int c,
                                            int arow, int ahalf, int tid,
                                            int n0, int m0,
                                            const float* __restrict__ pw,
                                            const float* __restrict__ pb) {
    uint32_t dst = sb + (buf ? OFF_STG1 : OFF_STG0) + arow * STGROW + ahalf * 128;
    const float* src = (c < 512)
        ? pw + (size_t)(n0 + arow) * KMAIN + (size_t)c * 64 + ahalf * 32
        : pb + (size_t)(n0 + arow) * NL + ahalf * 32;
    #pragma unroll
    for (int j = 0; j < 8; j++) CPA16(dst + j * 16, src + j * 4);
    if (c < 512 && tid < 32)
        CPA16(sb + (buf ? OFF_X1 : OFF_X0) + tid * 16,
              g_xT + (size_t)c * BSZ + m0 + tid * 4);
}

__device__ __forceinline__ void split8_store(const float* v, char* hip, char* lop) {
    // 8 fp32 -> 4x bf162 hi + 4x bf162 lo, one uint4 store each
    __nv_bfloat162 h0 = __floats2bfloat162_rn(v[0], v[1]);
    __nv_bfloat162 h1 = __floats2bfloat162_rn(v[2], v[3]);
    __nv_bfloat162 h2 = __floats2bfloat162_rn(v[4], v[5]);
    __nv_bfloat162 h3 = __floats2bfloat162_rn(v[6], v[7]);
    __nv_bfloat162 l0 = __floats2bfloat162_rn(v[0] - __bfloat162float(h0.x), v[1] - __bfloat162float(h0.y));
    __nv_bfloat162 l1 = __floats2bfloat162_rn(v[2] - __bfloat162float(h1.x), v[3] - __bfloat162float(h1.y));
    __nv_bfloat162 l2 = __floats2bfloat162_rn(v[4] - __bfloat162float(h2.x), v[5] - __bfloat162float(h2.y));
    __nv_bfloat162 l3 = __floats2bfloat162_rn(v[6] - __bfloat162float(h3.x), v[7] - __bfloat162float(h3.y));
    uint4 H = make_uint4(bits2(h0), bits2(h1), bits2(h2), bits2(h3));
    uint4 L = make_uint4(bits2(l0), bits2(l1), bits2(l2), bits2(l3));
    *reinterpret_cast<uint4*>(hip) = H;
    *reinterpret_cast<uint4*>(lop) = L;
}

__global__ void __launch_bounds__(NTHR, 1) hme_mma_kernel(
    const float* __restrict__ pw, const float* __restrict__ pb) {
    extern __shared__ char smem[];
    const uint32_t sb = smem_u32(smem);
    const int tid = threadIdx.x;
    const int lane = tid & 31, w = tid >> 5;
    const int n0 = blockIdx.x * TILE_N;
    const int m0 = blockIdx.y * TILE_M;
    const int s  = blockIdx.z;
    const int c0 = (s == 0) ? 0 : 129 + 128 * (s - 1);
    const int nch = (s == 0) ? 129 : 128;

    const int arow = tid & 127;       // row for staging/convert
    const int ahalf = tid >> 7;       // k-half (0/1)
    const int wm = w >> 2, wn = w & 3;   // warp tile: 64(M) x 32(N)

    // leaf probs resident in registers: p[m0+arow][ahalf*32 .. +31]
    float pr[32];
    {
        const float4* pp = reinterpret_cast<const float4*>(
            g_leafp + (size_t)(m0 + arow) * NL + ahalf * 32);
        #pragma unroll
        for (int j = 0; j < 8; j++) {
            float4 v = pp[j];
            pr[4*j] = v.x; pr[4*j+1] = v.y; pr[4*j+2] = v.z; pr[4*j+3] = v.w;
        }
    }

    float acc[4][4][4];
    #pragma unroll
    for (int a = 0; a < 4; a++)
        #pragma unroll
        for (int b = 0; b < 4; b++)
            #pragma unroll
            for (int d = 0; d < 4; d++) acc[a][b][d] = 0.f;

    issue_stage(sb, 0, c0, arow, ahalf, tid, n0, m0, pw, pb);
    CPCOMMIT();

    for (int it = 0; it < nch; ++it) {
        const int c = c0 + it;
        const int buf = it & 1;
        if (it + 1 < nch)
            issue_stage(sb, buf ^ 1, c + 1, arow, ahalf, tid, n0, m0, pw, pb);
        CPCOMMIT();
        CPWAIT1();                         // stage[buf] complete

        // ---- convert chunk c: stage[buf] fp32 -> bf16 tile set [buf]
        {
            const char* stg = smem + (buf ? OFF_STG1 : OFF_STG0)
                              + arow * STGROW + ahalf * 128;
            char* setb = smem + buf * SETSZ;
            char* Bh = setb + OFF_BHI + arow * ROWB + ahalf * 64;
            char* Bl = setb + OFF_BLO + arow * ROWB + ahalf * 64;
            #pragma unroll
            for (int q = 0; q < 4; q++) {
                float4 v0 = *reinterpret_cast<const float4*>(stg + q * 32);
                float4 v1 = *reinterpret_cast<const float4*>(stg + q * 32 + 16);
                float v[8] = {v0.x, v0.y, v0.z, v0.w, v1.x, v1.y, v1.z, v1.w};
                split8_store(v, Bh + q * 16, Bl + q * 16);
            }
            float xv = 1.0f;
            if (c < 512)
                xv = reinterpret_cast<const float*>(smem + (buf ? OFF_X1 : OFF_X0))[arow];
            char* Ah = setb + OFF_AHI + arow * ROWB + ahalf * 64;
            char* Al = setb + OFF_ALO + arow * ROWB + ahalf * 64;
            #pragma unroll
            for (int q = 0; q < 4; q++) {
                float v[8];
                #pragma unroll
                for (int j = 0; j < 8; j++) v[j] = xv * pr[q * 8 + j];
                split8_store(v, Ah + q * 16, Al + q * 16);
            }
        }

        // ---- MMA over chunk it-1 (tile set buf^1), overlapped with convert issue
        if (it > 0) {
            const uint32_t setb = sb + (buf ^ 1) * SETSZ;
            const int r = lane & 15, kh = lane >> 4;
            #pragma unroll
            for (int ks = 0; ks < 4; ks++) {
                const int kb = ks * 32 + kh * 16;   // byte offset in 128B row
                uint32_t ahi[4][4], alo[4][4], bhi[4][2], blo[4][2];
                #pragma unroll
                for (int mt = 0; mt < 4; mt++) {
                    uint32_t ad = setb + OFF_AHI + (64 * wm + 16 * mt + r) * ROWB + kb;
                    ldsm4(ahi[mt], ad);
                    ldsm4(alo[mt], ad + TILEB);
                }
                #pragma unroll
                for (int g = 0; g < 2; g++) {
                    uint32_t bd = setb + OFF_BHI + (32 * wn + 16 * g + r) * ROWB + kb;
                    uint32_t t[4];
                    ldsm4(t, bd);
                    bhi[2*g][0] = t[0]; bhi[2*g][1] = t[2];
                    bhi[2*g+1][0] = t[1]; bhi[2*g+1][1] = t[3];
                    ldsm4(t, bd + TILEB);
                    blo[2*g][0] = t[0]; blo[2*g][1] = t[2];
                    blo[2*g+1][0] = t[1]; blo[2*g+1][1] = t[3];
                }
                #pragma unroll
                for (int mt = 0; mt < 4; mt++)
                    #pragma unroll
                    for (int nt = 0; nt < 4; nt++) {
                        mma16816(acc[mt][nt], ahi[mt], bhi[nt]);
                        mma16816(acc[mt][nt], ahi[mt], blo[nt]);
                        mma16816(acc[mt][nt], alo[mt], bhi[nt]);
                    }
            }
        }
        __syncthreads();   // convert(it) done everywhere; set[buf^1] free for reuse
    }

    // ---- final chunk's MMA
    {
        const uint32_t setb = sb + ((nch - 1) & 1) * SETSZ;
        const int r = lane & 15, kh = lane >> 4;
        #pragma unroll
        for (int ks = 0; ks < 4; ks++) {
            const int kb = ks * 32 + kh * 16;
            uint32_t ahi[4][4], alo[4][4], bhi[4][2], blo[4][2];
            #pragma unroll
            for (int mt = 0; mt < 4; mt++) {
                uint32_t ad = setb + OFF_AHI + (64 * wm + 16 * mt + r) * ROWB + kb;
                ldsm4(ahi[mt], ad);
                ldsm4(alo[mt], ad + TILEB);
            }
            #pragma unroll
            for (int g = 0; g < 2; g++) {
                uint32_t bd = setb + OFF_BHI + (32 * wn + 16 * g + r) * ROWB + kb;
                uint32_t t[4];
                ldsm4(t, bd);
                bhi[2*g][0] = t[0]; bhi[2*g][1] = t[2];
                bhi[2*g+1][0] = t[1]; bhi[2*g+1][1] = t[3];
                ldsm4(t, bd + TILEB);
                blo[2*g][0] = t[0]; blo[2*g][1] = t[2];
                blo[2*g+1][0] = t[1]; blo[2*g+1][1] = t[3];
            }
            #pragma unroll
            for (int mt = 0; mt < 4; mt++)
                #pragma unroll
                for (int nt = 0; nt < 4; nt++) {
                    mma16816(acc[mt][nt], ahi[mt], bhi[nt]);
                    mma16816(acc[mt][nt], ahi[mt], blo[nt]);
                    mma16816(acc[mt][nt], alo[mt], bhi[nt]);
                }
        }
    }

    // ---- epilogue: partials to g_part[s]
    float* base = g_part + (size_t)s * (BSZ * OFT);
    #pragma unroll
    for (int mt = 0; mt < 4; mt++) {
        int m = m0 + 64 * wm + 16 * mt + (lane >> 2);
        #pragma unroll
        for (int nt = 0; nt < 4; nt++) {
            int n = n0 + 32 * wn + 8 * nt + (lane & 3) * 2;
            *reinterpret_cast<float2*>(base + (size_t)m * OFT + n) =
                make_float2(acc[mt][nt][0], acc[mt][nt][1]);
            *reinterpret_cast<float2*>(base + (size_t)(m + 8) * OFT + n) =
                make_float2(acc[mt][nt][2], acc[mt][nt][3]);
        }
    }
}

// ---------------------------------------------------------------------------
// Reduce K-split partials -> out
// ---------------------------------------------------------------------------
__global__ void reduce_kernel(float* __restrict__ out) {
    const int i = blockIdx.x * blockDim.x + threadIdx.x;
    const float4* p = reinterpret_cast<const float4*>(g_part);
    float4 a = p[i];
    #pragma unroll
    for (int s = 1; s < KSPLIT; s++) {
        float4 b = p[(size_t)s * ((BSZ * OFT) / 4) + i];
        a.x += b.x; a.y += b.y; a.z += b.z; a.w += b.w;
    }
    reinterpret_cast<float4*>(out)[i] = a;
}

// ---------------------------------------------------------------------------
extern "C" void kernel_launch(void* const* d_in, const int* in_sizes, int n_in,
                              void* d_out, int out_size) {
    const float* xg = (const float*)d_in[0];  // x_gating [1024,512]
    const float* xl = (const float*)d_in[1];  // x_leaf   [1024,512]
    const float* gw = (const float*)d_in[2];  // [512,63]
    const float* gb = (const float*)d_in[3];  // [63]
    const float* pw = (const float*)d_in[4];  // [512,512,64]
    const float* pb = (const float*)d_in[5];  // [512,64]
    float* out = (float*)d_out;               // [1024,512] f32

    cudaFuncSetAttribute(hme_mma_kernel,
                         cudaFuncAttributeMaxDynamicSharedMemorySize, SMEM_SZ);

    leaf_probs_kernel<<<BSZ, 128>>>(xg, gw, gb);
    transpose_kernel<<<dim3(IFT / 32, BSZ / 32), dim3(32, 8)>>>(xl);

    dim3 grid(OFT / TILE_N, BSZ / TILE_M, KSPLIT);   // (4, 8, 4) = 128 CTAs
    hme_mma_kernel<<<grid, NTHR, SMEM_SZ>>>(pw, pb);

    reduce_kernel<<<(BSZ * OFT / 4) / 256, 256>>>(out);
}

// round 5
// speedup vs baseline: 6.4128x; 1.7353x over previous
#include <cuda_runtime.h>
#include <cuda_fp16.h>
#include <cstdint>

#define BSZ 1024
#define GF 512
#define IFT 512
#define OFT 512
#define NL 64
#define GC 63
#define KMAIN (IFT * NL)          // 32768
#define KSPLIT 4
#define TILE_M 128
#define TILE_N 128
#define NTHR 256

// ---------------------------------------------------------------------------
// static device scratch
// ---------------------------------------------------------------------------
__device__ __align__(256) float g_leafp[BSZ * NL];                  // 256KB
__device__ __align__(256) float g_xT[IFT * BSZ];                    // 2MB
__device__ __align__(256) float g_part[(size_t)KSPLIT * BSZ * OFT]; // 8MB

// ---------------------------------------------------------------------------
// smem layout: 2 fp16 tile-sets (A|B) + 2 fp32 B-stages + 2 x-columns
// ---------------------------------------------------------------------------
#define ROWB 144                    // fp16 tile row stride (64*2 + 16 pad)
#define TILEB (128 * ROWB)          // 18432
#define SETSZ (2 * TILEB)           // A | B = 36864
#define OFF_A 0
#define OFF_B TILEB
#define STGROW 272                  // fp32 stage row stride (64*4 + 16 pad)
#define STGSZ (128 * STGROW)        // 34816
#define OFF_STG0 (2 * SETSZ)        // 73728
#define OFF_STG1 (OFF_STG0 + STGSZ)
#define OFF_X0   (OFF_STG1 + STGSZ)
#define OFF_X1   (OFF_X0 + 512)
#define SMEM_SZ  (OFF_X1 + 512)     // 144384

// ---------------------------------------------------------------------------
// PTX helpers (base sm_103 target only — no 'a'-gated instructions)
// ---------------------------------------------------------------------------
__device__ __forceinline__ uint32_t smem_u32(const void* p) {
    uint32_t a;
    asm("{ .reg .u64 t; cvta.to.shared.u64 t, %1; cvt.u32.u64 %0, t; }" : "=r"(a) : "l"(p));
    return a;
}
#define CPA16(dst, src) \
    asm volatile("cp.async.cg.shared.global [%0], [%1], 16;" :: "r"(dst), "l"(src) : "memory")
#define CPCOMMIT() asm volatile("cp.async.commit_group;" ::: "memory")
#define CPWAIT1()  asm volatile("cp.async.wait_group 1;" ::: "memory")

__device__ __forceinline__ void ldsm4(uint32_t (&r)[4], uint32_t a) {
    asm volatile("ldmatrix.sync.aligned.m8n8.x4.shared.b16 {%0,%1,%2,%3}, [%4];"
        : "=r"(r[0]), "=r"(r[1]), "=r"(r[2]), "=r"(r[3]) : "r"(a));
}
__device__ __forceinline__ void mma16816(float* d, const uint32_t* a, const uint32_t* b) {
    asm volatile("mma.sync.aligned.m16n8k16.row.col.f32.f16.f16.f32 "
        "{%0,%1,%2,%3}, {%4,%5,%6,%7}, {%8,%9}, {%0,%1,%2,%3};"
        : "+f"(d[0]), "+f"(d[1]), "+f"(d[2]), "+f"(d[3])
        : "r"(a[0]), "r"(a[1]), "r"(a[2]), "r"(a[3]), "r"(b[0]), "r"(b[1]));
}
__device__ __forceinline__ uint32_t hbits2(__half2 h) {
    return *reinterpret_cast<uint32_t*>(&h);
}

// ---------------------------------------------------------------------------
// Kernel 1: gating GEMV + sigmoid + tree product -> g_leafp
// ---------------------------------------------------------------------------
__global__ void leaf_probs_kernel(const float* __restrict__ xg,
                                  const float* __restrict__ gw,
                                  const float* __restrict__ gb) {
    __shared__ float xs[GF];
    __shared__ float sg[GC];
    const int b = blockIdx.x;
    const int tid = threadIdx.x;
    for (int f = tid; f < GF; f += 128) xs[f] = xg[b * GF + f];
    __syncthreads();
    if (tid < GC) {
        float a0 = 0.f, a1 = 0.f, a2 = 0.f, a3 = 0.f;
        #pragma unroll 4
        for (int f = 0; f < GF; f += 4) {
            a0 += xs[f + 0] * gw[(f + 0) * GC + tid];
            a1 += xs[f + 1] * gw[(f + 1) * GC + tid];
            a2 += xs[f + 2] * gw[(f + 2) * GC + tid];
            a3 += xs[f + 3] * gw[(f + 3) * GC + tid];
        }
        float z = (a0 + a1) + (a2 + a3) + gb[tid];
        sg[tid] = 1.f / (1.f + expf(-z));
    }
    __syncthreads();
    if (tid < NL) {
        const int l = tid;
        float p = 1.f;
        #pragma unroll
        for (int d = 0; d < 6; d++) {
            int node = l >> (6 - d);
            int idx  = (1 << d) - 1 + node;
            int bit  = (l >> (5 - d)) & 1;
            float g = sg[idx];
            p *= bit ? (1.f - g) : g;
        }
        g_leafp[b * NL + l] = p;
    }
}

// ---------------------------------------------------------------------------
// Kernel 2: transpose x_leaf [B, IFT] -> g_xT [IFT, B]
// ---------------------------------------------------------------------------
__global__ void transpose_kernel(const float* __restrict__ x) {
    __shared__ float t[32][33];
    int i0 = blockIdx.x * 32, b0 = blockIdx.y * 32;
    for (int r = threadIdx.y; r < 32; r += 8)
        t[r][threadIdx.x] = x[(size_t)(b0 + r) * IFT + i0 + threadIdx.x];
    __syncthreads();
    for (int r = threadIdx.y; r < 32; r += 8)
        g_xT[(size_t)(i0 + r) * BSZ + b0 + threadIdx.x] = t[threadIdx.x][r];
}

// ---------------------------------------------------------------------------
// Main GEMM: single-fp16 mma.sync, cp.async 3-stage pipeline
// ---------------------------------------------------------------------------
__device__ __forceinline__ void issue_stage(uint32_t sb, int buf, int c,
                                            int arow, int ahalf, int tid,
                                            int n0, int m0,
                                            const float* __restrict__ pw,
                                            const float* __restrict__ pb) {
    uint32_t dst = sb + (buf ? OFF_STG1 : OFF_STG0) + arow * STGROW + ahalf * 128;
    const float* src = (c < 512)
        ? pw + (size_t)(n0 + arow) * KMAIN + (size_t)c * 64 + ahalf * 32
        : pb + (size_t)(n0 + arow) * NL + ahalf * 32;
    #pragma unroll
    for (int j = 0; j < 8; j++) CPA16(dst + j * 16, src + j * 4);
    if (c < 512 && tid < 32)
        CPA16(sb + (buf ? OFF_X1 : OFF_X0) + tid * 16,
              g_xT + (size_t)c * BSZ + m0 + tid * 4);
}

__device__ __forceinline__ void pack8_store(const float* v, char* dst) {
    __half2 h0 = __floats2half2_rn(v[0], v[1]);
    __half2 h1 = __floats2half2_rn(v[2], v[3]);
    __half2 h2 = __floats2half2_rn(v[4], v[5]);
    __half2 h3 = __floats2half2_rn(v[6], v[7]);
    *reinterpret_cast<uint4*>(dst) = make_uint4(hbits2(h0), hbits2(h1), hbits2(h2), hbits2(h3));
}

__global__ void __launch_bounds__(NTHR, 1) hme_mma_kernel(
    const float* __restrict__ pw, const float* __restrict__ pb) {
    extern __shared__ char smem[];
    const uint32_t sb = smem_u32(smem);
    const int tid = threadIdx.x;
    const int lane = tid & 31, w = tid >> 5;
    const int n0 = blockIdx.x * TILE_N;
    const int m0 = blockIdx.y * TILE_M;
    const int s  = blockIdx.z;
    const int c0 = (s == 0) ? 0 : 129 + 128 * (s - 1);
    const int nch = (s == 0) ? 129 : 128;

    const int arow = tid & 127;       // staging/convert row
    const int ahalf = tid >> 7;       // k-half (0/1)
    const int wm = w >> 2, wn = w & 3;   // warp tile: 64(M) x 32(N)

    // leaf probs in registers: p[m0+arow][ahalf*32 .. +31]
    float pr[32];
    {
        const float4* pp = reinterpret_cast<const float4*>(
            g_leafp + (size_t)(m0 + arow) * NL + ahalf * 32);
        #pragma unroll
        for (int j = 0; j < 8; j++) {
            float4 v = pp[j];
            pr[4*j] = v.x; pr[4*j+1] = v.y; pr[4*j+2] = v.z; pr[4*j+3] = v.w;
        }
    }

    float acc[4][4][4];
    #pragma unroll
    for (int a = 0; a < 4; a++)
        #pragma unroll
        for (int b = 0; b < 4; b++)
            #pragma unroll
            for (int d = 0; d < 4; d++) acc[a][b][d] = 0.f;

    issue_stage(sb, 0, c0, arow, ahalf, tid, n0, m0, pw, pb);
    CPCOMMIT();

    for (int it = 0; it < nch; ++it) {
        const int c = c0 + it;
        const int buf = it & 1;
        if (it + 1 < nch)
            issue_stage(sb, buf ^ 1, c + 1, arow, ahalf, tid, n0, m0, pw, pb);
        CPCOMMIT();
        CPWAIT1();                         // stage[buf] complete

        // ---- convert chunk c -> fp16 tile set [buf]
        {
            const char* stg = smem + (buf ? OFF_STG1 : OFF_STG0)
                              + arow * STGROW + ahalf * 128;
            char* setb = smem + buf * SETSZ;
            char* Bt = setb + OFF_B + arow * ROWB + ahalf * 64;
            #pragma unroll
            for (int q = 0; q < 4; q++) {
                float4 v0 = *reinterpret_cast<const float4*>(stg + q * 32);
                float4 v1 = *reinterpret_cast<const float4*>(stg + q * 32 + 16);
                float v[8] = {v0.x, v0.y, v0.z, v0.w, v1.x, v1.y, v1.z, v1.w};
                pack8_store(v, Bt + q * 16);
            }
            float xv = 1.0f;
            if (c < 512)
                xv = reinterpret_cast<const float*>(smem + (buf ? OFF_X1 : OFF_X0))[arow];
            char* At = setb + OFF_A + arow * ROWB + ahalf * 64;
            #pragma unroll
            for (int q = 0; q < 4; q++) {
                float v[8];
                #pragma unroll
                for (int j = 0; j < 8; j++) v[j] = xv * pr[q * 8 + j];
                pack8_store(v, At + q * 16);
            }
        }

        // ---- MMA over chunk it-1 (tile set buf^1), overlapped with staging
        if (it > 0) {
            const uint32_t setb = sb + (buf ^ 1) * SETSZ;
            const int r = lane & 15, kh = lane >> 4;
            #pragma unroll
            for (int ks = 0; ks < 4; ks++) {
                const int kb = ks * 32 + kh * 16;   // byte offset in 128B row
                uint32_t av[4][4], bv[4][2];
                #pragma unroll
                for (int mt = 0; mt < 4; mt++)
                    ldsm4(av[mt], setb + OFF_A + (64 * wm + 16 * mt + r) * ROWB + kb);
                #pragma unroll
                for (int g = 0; g < 2; g++) {
                    uint32_t t[4];
                    ldsm4(t, setb + OFF_B + (32 * wn + 16 * g + r) * ROWB + kb);
                    bv[2*g][0] = t[0]; bv[2*g][1] = t[2];
                    bv[2*g+1][0] = t[1]; bv[2*g+1][1] = t[3];
                }
                #pragma unroll
                for (int mt = 0; mt < 4; mt++)
                    #pragma unroll
                    for (int nt = 0; nt < 4; nt++)
                        mma16816(acc[mt][nt], av[mt], bv[nt]);
            }
        }
        __syncthreads();   // convert(it) visible; set[buf^1] free for reuse
    }

    // ---- final chunk's MMA
    {
        const uint32_t setb = sb + ((nch - 1) & 1) * SETSZ;
        const int r = lane & 15, kh = lane >> 4;
        #pragma unroll
        for (int ks = 0; ks < 4; ks++) {
            const int kb = ks * 32 + kh * 16;
            uint32_t av[4][4], bv[4][2];
            #pragma unroll
            for (int mt = 0; mt < 4; mt++)
                ldsm4(av[mt], setb + OFF_A + (64 * wm + 16 * mt + r) * ROWB + kb);
            #pragma unroll
            for (int g = 0; g < 2; g++) {
                uint32_t t[4];
                ldsm4(t, setb + OFF_B + (32 * wn + 16 * g + r) * ROWB + kb);
                bv[2*g][0] = t[0]; bv[2*g][1] = t[2];
                bv[2*g+1][0] = t[1]; bv[2*g+1][1] = t[3];
            }
            #pragma unroll
            for (int mt = 0; mt < 4; mt++)
                #pragma unroll
                for (int nt = 0; nt < 4; nt++)
                    mma16816(acc[mt][nt], av[mt], bv[nt]);
        }
    }

    // ---- epilogue: partials to g_part[s]
    float* base = g_part + (size_t)s * (BSZ * OFT);
    #pragma unroll
    for (int mt = 0; mt < 4; mt++) {
        int m = m0 + 64 * wm + 16 * mt + (lane >> 2);
        #pragma unroll
        for (int nt = 0; nt < 4; nt++) {
            int n = n0 + 32 * wn + 8 * nt + (lane & 3) * 2;
            *reinterpret_cast<float2*>(base + (size_t)m * OFT + n) =
                make_float2(acc[mt][nt][0], acc[mt][nt][1]);
            *reinterpret_cast<float2*>(base + (size_t)(m + 8) * OFT + n) =
                make_float2(acc[mt][nt][2], acc[mt][nt][3]);
        }
    }
}

// ---------------------------------------------------------------------------
// Reduce K-split partials -> out
// ---------------------------------------------------------------------------
__global__ void reduce_kernel(float* __restrict__ out) {
    const int i = blockIdx.x * blockDim.x + threadIdx.x;
    const float4* p = reinterpret_cast<const float4*>(g_part);
    float4 a = p[i];
    #pragma unroll
    for (int s = 1; s < KSPLIT; s++) {
        float4 b = p[(size_t)s * ((BSZ * OFT) / 4) + i];
        a.x += b.x; a.y += b.y; a.z += b.z; a.w += b.w;
    }
    reinterpret_cast<float4*>(out)[i] = a;
}

// ---------------------------------------------------------------------------
extern "C" void kernel_launch(void* const* d_in, const int* in_sizes, int n_in,
                              void* d_out, int out_size) {
    const float* xg = (const float*)d_in[0];  // x_gating [1024,512]
    const float* xl = (const float*)d_in[1];  // x_leaf   [1024,512]
    const float* gw = (const float*)d_in[2];  // [512,63]
    const float* gb = (const float*)d_in[3];  // [63]
    const float* pw = (const float*)d_in[4];  // [512,512,64]
    const float* pb = (const float*)d_in[5];  // [512,64]
    float* out = (float*)d_out;               // [1024,512] f32

    cudaFuncSetAttribute(hme_mma_kernel,
                         cudaFuncAttributeMaxDynamicSharedMemorySize, SMEM_SZ);

    leaf_probs_kernel<<<BSZ, 128>>>(xg, gw, gb);
    transpose_kernel<<<dim3(IFT / 32, BSZ / 32), dim3(32, 8)>>>(xl);

    dim3 grid(OFT / TILE_N, BSZ / TILE_M, KSPLIT);   // (4, 8, 4) = 128 CTAs
    hme_mma_kernel<<<grid, NTHR, SMEM_SZ>>>(pw, pb);

    reduce_kernel<<<(BSZ * OFT / 4) / 256, 256>>>(out);
}

// round 6
// speedup vs baseline: 7.5701x; 1.1805x over previous
#include <cuda_runtime.h>
#include <cuda_fp16.h>
#include <cstdint>

#define BSZ 1024
#define GF 512
#define IFT 512
#define OFT 512
#define NL 64
#define GC 63
#define KMAIN (IFT * NL)          // 32768
#define KSPLIT 4
#define TILE_M 128
#define TILE_N 128
#define NTHR 384                  // 8 consumer warps + 4 producer warps

// ---------------------------------------------------------------------------
// static device scratch
// ---------------------------------------------------------------------------
__device__ __align__(256) float g_leafp[BSZ * NL];                  // 256KB
__device__ __align__(256) float g_xT[IFT * BSZ];                    // 2MB
__device__ __align__(256) float g_part[(size_t)KSPLIT * BSZ * OFT]; // 8MB

// ---------------------------------------------------------------------------
// smem layout: 2 fp16 tile-sets (A|B) + 2 fp32 B-stages
// ---------------------------------------------------------------------------
#define ROWB 144                    // fp16 tile row stride (64*2 + 16 pad)
#define TILEB (128 * ROWB)          // 18432
#define SETSZ (2 * TILEB)           // A | B = 36864
#define OFF_A 0
#define OFF_B TILEB
#define STGROW 272                  // fp32 stage row stride (64*4 + 16 pad)
#define STGSZ (128 * STGROW)        // 34816
#define OFF_STG0 (2 * SETSZ)        // 73728
#define OFF_STG1 (OFF_STG0 + STGSZ)
#define SMEM_SZ  (OFF_STG1 + STGSZ) // 143360

// named barriers (0 = __syncthreads default; use 1..4)
#define BARF0 1
#define BARF1 2
#define BARE0 3
#define BARE1 4
#define BAR_SYNC(id)   asm volatile("bar.sync %0, %1;"   :: "r"(id), "r"(NTHR) : "memory")
#define BAR_ARRIVE(id) asm volatile("bar.arrive %0, %1;" :: "r"(id), "r"(NTHR) : "memory")

// ---------------------------------------------------------------------------
// PTX helpers (base sm_103 target only — no 'a'-gated instructions)
// ---------------------------------------------------------------------------
__device__ __forceinline__ uint32_t smem_u32(const void* p) {
    uint32_t a;
    asm("{ .reg .u64 t; cvta.to.shared.u64 t, %1; cvt.u32.u64 %0, t; }" : "=r"(a) : "l"(p));
    return a;
}
#define CPA16(dst, src) \
    asm volatile("cp.async.cg.shared.global [%0], [%1], 16;" :: "r"(dst), "l"(src) : "memory")
#define CPCOMMIT() asm volatile("cp.async.commit_group;" ::: "memory")
#define CPWAIT1()  asm volatile("cp.async.wait_group 1;" ::: "memory")

__device__ __forceinline__ void ldsm4(uint32_t (&r)[4], uint32_t a) {
    asm volatile("ldmatrix.sync.aligned.m8n8.x4.shared.b16 {%0,%1,%2,%3}, [%4];"
        : "=r"(r[0]), "=r"(r[1]), "=r"(r[2]), "=r"(r[3]) : "r"(a));
}
__device__ __forceinline__ void mma16816(float* d, const uint32_t* a, const uint32_t* b) {
    asm volatile("mma.sync.aligned.m16n8k16.row.col.f32.f16.f16.f32 "
        "{%0,%1,%2,%3}, {%4,%5,%6,%7}, {%8,%9}, {%0,%1,%2,%3};"
        : "+f"(d[0]), "+f"(d[1]), "+f"(d[2]), "+f"(d[3])
        : "r"(a[0]), "r"(a[1]), "r"(a[2]), "r"(a[3]), "r"(b[0]), "r"(b[1]));
}
__device__ __forceinline__ uint32_t hbits2(__half2 h) {
    return *reinterpret_cast<uint32_t*>(&h);
}
__device__ __forceinline__ void pack8_store(const float* v, char* dst) {
    __half2 h0 = __floats2half2_rn(v[0], v[1]);
    __half2 h1 = __floats2half2_rn(v[2], v[3]);
    __half2 h2 = __floats2half2_rn(v[4], v[5]);
    __half2 h3 = __floats2half2_rn(v[6], v[7]);
    *reinterpret_cast<uint4*>(dst) = make_uint4(hbits2(h0), hbits2(h1), hbits2(h2), hbits2(h3));
}

// ---------------------------------------------------------------------------
// Kernel 1: gating GEMV + sigmoid + tree product -> g_leafp
// ---------------------------------------------------------------------------
__global__ void leaf_probs_kernel(const float* __restrict__ xg,
                                  const float* __restrict__ gw,
                                  const float* __restrict__ gb) {
    __shared__ float xs[GF];
    __shared__ float sg[GC];
    const int b = blockIdx.x;
    const int tid = threadIdx.x;
    for (int f = tid; f < GF; f += 128) xs[f] = xg[b * GF + f];
    __syncthreads();
    if (tid < GC) {
        float a0 = 0.f, a1 = 0.f, a2 = 0.f, a3 = 0.f;
        #pragma unroll 4
        for (int f = 0; f < GF; f += 4) {
            a0 += xs[f + 0] * gw[(f + 0) * GC + tid];
            a1 += xs[f + 1] * gw[(f + 1) * GC + tid];
            a2 += xs[f + 2] * gw[(f + 2) * GC + tid];
            a3 += xs[f + 3] * gw[(f + 3) * GC + tid];
        }
        float z = (a0 + a1) + (a2 + a3) + gb[tid];
        sg[tid] = 1.f / (1.f + expf(-z));
    }
    __syncthreads();
    if (tid < NL) {
        const int l = tid;
        float p = 1.f;
        #pragma unroll
        for (int d = 0; d < 6; d++) {
            int node = l >> (6 - d);
            int idx  = (1 << d) - 1 + node;
            int bit  = (l >> (5 - d)) & 1;
            float g = sg[idx];
            p *= bit ? (1.f - g) : g;
        }
        g_leafp[b * NL + l] = p;
    }
}

// ---------------------------------------------------------------------------
// Kernel 2: transpose x_leaf [B, IFT] -> g_xT [IFT, B]
// ---------------------------------------------------------------------------
__global__ void transpose_kernel(const float* __restrict__ x) {
    __shared__ float t[32][33];
    int i0 = blockIdx.x * 32, b0 = blockIdx.y * 32;
    for (int r = threadIdx.y; r < 32; r += 8)
        t[r][threadIdx.x] = x[(size_t)(b0 + r) * IFT + i0 + threadIdx.x];
    __syncthreads();
    for (int r = threadIdx.y; r < 32; r += 8)
        g_xT[(size_t)(i0 + r) * BSZ + b0 + threadIdx.x] = t[threadIdx.x][r];
}

// ---------------------------------------------------------------------------
// Main GEMM: warp-specialized producer/consumer, single-fp16 mma.sync
// ---------------------------------------------------------------------------
__device__ __forceinline__ void stage_issue(uint32_t sb, int buf, int c, int pt,
                                            int n0,
                                            const float* __restrict__ pw,
                                            const float* __restrict__ pb) {
    uint32_t dst = sb + (buf ? OFF_STG1 : OFF_STG0) + pt * STGROW;
    const float* src = (c < 512)
        ? pw + (size_t)(n0 + pt) * KMAIN + (size_t)c * 64
        : pb + (size_t)(n0 + pt) * NL;
    #pragma unroll
    for (int j = 0; j < 16; j++) CPA16(dst + j * 16, src + j * 4);
}

__device__ __forceinline__ void mma_chunk(uint32_t setb, int wm, int wn, int lane,
                                          float (*acc)[4][4]) {
    const int r = lane & 15, kh = lane >> 4;
    #pragma unroll
    for (int ks = 0; ks < 4; ks++) {
        const int kb = ks * 32 + kh * 16;   // byte offset within 128B row
        uint32_t av[4][4], bv[4][2];
        #pragma unroll
        for (int mt = 0; mt < 4; mt++)
            ldsm4(av[mt], setb + OFF_A + (64 * wm + 16 * mt + r) * ROWB + kb);
        #pragma unroll
        for (int g = 0; g < 2; g++) {
            uint32_t t[4];
            ldsm4(t, setb + OFF_B + (32 * wn + 16 * g + r) * ROWB + kb);
            bv[2*g][0] = t[0];   bv[2*g][1] = t[2];
            bv[2*g+1][0] = t[1]; bv[2*g+1][1] = t[3];
        }
        #pragma unroll
        for (int mt = 0; mt < 4; mt++)
            #pragma unroll
            for (int nt = 0; nt < 4; nt++)
                mma16816(acc[mt][nt], av[mt], bv[nt]);
    }
}

__global__ void __launch_bounds__(NTHR, 1) hme_mma_kernel(
    const float* __restrict__ pw, const float* __restrict__ pb) {
    extern __shared__ char smem[];
    const uint32_t sb = smem_u32(smem);
    const int tid = threadIdx.x;
    const int lane = tid & 31, w = tid >> 5;
    const int n0 = blockIdx.x * TILE_N;
    const int m0 = blockIdx.y * TILE_M;
    const int s  = blockIdx.z;
    const int c0 = (s == 0) ? 0 : 129 + 128 * (s - 1);
    const int nch = (s == 0) ? 129 : 128;

    if (w < 8) {
        // ================= CONSUMERS: MMA only =================
        const int wm = w >> 2, wn = w & 3;   // warp tile: 64(M) x 32(N)
        float acc[4][4][4];
        #pragma unroll
        for (int a = 0; a < 4; a++)
            #pragma unroll
            for (int b = 0; b < 4; b++)
                #pragma unroll
                for (int d = 0; d < 4; d++) acc[a][b][d] = 0.f;

        for (int it = 0; it < nch; ++it) {
            const int buf = it & 1;
            BAR_SYNC(BARF0 + buf);            // wait tiles[buf] full
            mma_chunk(sb + buf * SETSZ, wm, wn, lane, acc);
            BAR_ARRIVE(BARE0 + buf);          // tiles[buf] free
        }

        // epilogue: partials to g_part[s]
        float* base = g_part + (size_t)s * (BSZ * OFT);
        #pragma unroll
        for (int mt = 0; mt < 4; mt++) {
            int m = m0 + 64 * wm + 16 * mt + (lane >> 2);
            #pragma unroll
            for (int nt = 0; nt < 4; nt++) {
                int n = n0 + 32 * wn + 8 * nt + (lane & 3) * 2;
                *reinterpret_cast<float2*>(base + (size_t)m * OFT + n) =
                    make_float2(acc[mt][nt][0], acc[mt][nt][1]);
                *reinterpret_cast<float2*>(base + (size_t)(m + 8) * OFT + n) =
                    make_float2(acc[mt][nt][2], acc[mt][nt][3]);
            }
        }
    } else {
        // ================= PRODUCERS: stage + convert =================
        const int pt = tid - 256;             // 0..127: one tile row per thread
        // leaf probs resident: p[m0+pt][0..63]
        float pr[64];
        {
            const float4* pp = reinterpret_cast<const float4*>(
                g_leafp + (size_t)(m0 + pt) * NL);
            #pragma unroll
            for (int j = 0; j < 16; j++) {
                float4 v = pp[j];
                pr[4*j] = v.x; pr[4*j+1] = v.y; pr[4*j+2] = v.z; pr[4*j+3] = v.w;
            }
        }

        stage_issue(sb, 0, c0, pt, n0, pw, pb);
        CPCOMMIT();

        for (int it = 0; it < nch; ++it) {
            const int c = c0 + it;
            const int buf = it & 1;
            if (it + 1 < nch)
                stage_issue(sb, buf ^ 1, c + 1, pt, n0, pw, pb);
            CPCOMMIT();
            CPWAIT1();                        // stage[buf] landed (thread-local rows)

            // x value for this chunk (coalesced 512B LDG, L2-resident)
            float xv = 1.0f;
            if (c < 512) xv = g_xT[(size_t)c * BSZ + m0 + pt];

            if (it >= 2) BAR_SYNC(BARE0 + buf);   // consumers done with tiles[buf]

            // convert: stage fp32 row -> fp16 B row; registers -> fp16 A row
            const char* stg = smem + (buf ? OFF_STG1 : OFF_STG0) + pt * STGROW;
            char* setb = smem + buf * SETSZ;
            char* Bt = setb + OFF_B + pt * ROWB;
            char* At = setb + OFF_A + pt * ROWB;
            #pragma unroll
            for (int q = 0; q < 8; q++) {
                float4 v0 = *reinterpret_cast<const float4*>(stg + q * 32);
                float4 v1 = *reinterpret_cast<const float4*>(stg + q * 32 + 16);
                float v[8] = {v0.x, v0.y, v0.z, v0.w, v1.x, v1.y, v1.z, v1.w};
                pack8_store(v, Bt + q * 16);
            }
            #pragma unroll
            for (int q = 0; q < 8; q++) {
                float v[8];
                #pragma unroll
                for (int j = 0; j < 8; j++) v[j] = xv * pr[q * 8 + j];
                pack8_store(v, At + q * 16);
            }

            BAR_ARRIVE(BARF0 + buf);          // tiles[buf] full
        }
    }
}

// ---------------------------------------------------------------------------
// Reduce K-split partials -> out
// ---------------------------------------------------------------------------
__global__ void reduce_kernel(float* __restrict__ out) {
    const int i = blockIdx.x * blockDim.x + threadIdx.x;
    const float4* p = reinterpret_cast<const float4*>(g_part);
    float4 a = p[i];
    #pragma unroll
    for (int s = 1; s < KSPLIT; s++) {
        float4 b = p[(size_t)s * ((BSZ * OFT) / 4) + i];
        a.x += b.x; a.y += b.y; a.z += b.z; a.w += b.w;
    }
    reinterpret_cast<float4*>(out)[i] = a;
}

// ---------------------------------------------------------------------------
extern "C" void kernel_launch(void* const* d_in, const int* in_sizes, int n_in,
                              void* d_out, int out_size) {
    const float* xg = (const float*)d_in[0];  // x_gating [1024,512]
    const float* xl = (const float*)d_in[1];  // x_leaf   [1024,512]
    const float* gw = (const float*)d_in[2];  // [512,63]
    const float* gb = (const float*)d_in[3];  // [63]
    const float* pw = (const float*)d_in[4];  // [512,512,64]
    const float* pb = (const float*)d_in[5];  // [512,64]
    float* out = (float*)d_out;               // [1024,512] f32

    cudaFuncSetAttribute(hme_mma_kernel,
                         cudaFuncAttributeMaxDynamicSharedMemorySize, SMEM_SZ);

    leaf_probs_kernel<<<BSZ, 128>>>(xg, gw, gb);
    transpose_kernel<<<dim3(IFT / 32, BSZ / 32), dim3(32, 8)>>>(xl);

    dim3 grid(OFT / TILE_N, BSZ / TILE_M, KSPLIT);   // (4, 8, 4) = 128 CTAs
    hme_mma_kernel<<<grid, NTHR, SMEM_SZ>>>(pw, pb);

    reduce_kernel<<<(BSZ * OFT / 4) / 256, 256>>>(out);
}

// round 7
// speedup vs baseline: 7.9349x; 1.0482x over previous
#include <cuda_runtime.h>
#include <cuda_fp16.h>
#include <cstdint>

#define BSZ 1024
#define GF 512
#define IFT 512
#define OFT 512
#define NL 64
#define GC 63
#define KMAIN (IFT * NL)          // 32768
#define KSPLIT 4
#define TILE_M 128
#define TILE_N 128
#define NTHR 384                  // 8 consumer warps + 4 producer warps
#define NBUF 3

// ---------------------------------------------------------------------------
// static device scratch
// ---------------------------------------------------------------------------
__device__ __align__(256) float g_leafp[BSZ * NL];                  // 256KB
__device__ __align__(256) float g_xT[IFT * BSZ];                    // 2MB
__device__ __align__(256) float g_part[(size_t)KSPLIT * BSZ * OFT]; // 8MB

// ---------------------------------------------------------------------------
// smem layout: 3 fp16 tile-sets (A|B) + 2 fp32 B-stages
// ---------------------------------------------------------------------------
#define ROWB 144                    // fp16 tile row stride (64*2 + 16 pad)
#define TILEB (128 * ROWB)          // 18432
#define SETSZ (2 * TILEB)           // A | B = 36864
#define OFF_A 0
#define OFF_B TILEB
#define STGROW 272                  // fp32 stage row stride (64*4 + 16 pad)
#define STGSZ (128 * STGROW)        // 34816
#define OFF_STG0 (NBUF * SETSZ)     // 110592
#define OFF_STG1 (OFF_STG0 + STGSZ)
#define SMEM_SZ  (OFF_STG1 + STGSZ) // 180224

// named barriers: full[0..2] = 1..3, empty[0..2] = 4..6
#define BARF(b) (1 + (b))
#define BARE(b) (4 + (b))
#define BAR_SYNC(id)   asm volatile("bar.sync %0, %1;"   :: "r"(id), "r"(NTHR) : "memory")
#define BAR_ARRIVE(id) asm volatile("bar.arrive %0, %1;" :: "r"(id), "r"(NTHR) : "memory")

// ---------------------------------------------------------------------------
// PTX helpers (base sm_103 target only — no 'a'-gated instructions)
// ---------------------------------------------------------------------------
__device__ __forceinline__ uint32_t smem_u32(const void* p) {
    uint32_t a;
    asm("{ .reg .u64 t; cvta.to.shared.u64 t, %1; cvt.u32.u64 %0, t; }" : "=r"(a) : "l"(p));
    return a;
}
#define CPA16(dst, src) \
    asm volatile("cp.async.cg.shared.global [%0], [%1], 16;" :: "r"(dst), "l"(src) : "memory")
#define CPCOMMIT() asm volatile("cp.async.commit_group;" ::: "memory")
#define CPWAIT1()  asm volatile("cp.async.wait_group 1;" ::: "memory")

__device__ __forceinline__ void ldsm4(uint32_t (&r)[4], uint32_t a) {
    asm volatile("ldmatrix.sync.aligned.m8n8.x4.shared.b16 {%0,%1,%2,%3}, [%4];"
        : "=r"(r[0]), "=r"(r[1]), "=r"(r[2]), "=r"(r[3]) : "r"(a));
}
__device__ __forceinline__ void mma16816(float* d, const uint32_t* a, const uint32_t* b) {
    asm volatile("mma.sync.aligned.m16n8k16.row.col.f32.f16.f16.f32 "
        "{%0,%1,%2,%3}, {%4,%5,%6,%7}, {%8,%9}, {%0,%1,%2,%3};"
        : "+f"(d[0]), "+f"(d[1]), "+f"(d[2]), "+f"(d[3])
        : "r"(a[0]), "r"(a[1]), "r"(a[2]), "r"(a[3]), "r"(b[0]), "r"(b[1]));
}
__device__ __forceinline__ uint32_t hbits2(__half2 h) {
    return *reinterpret_cast<uint32_t*>(&h);
}
__device__ __forceinline__ void pack8_store(const float* v, char* dst) {
    __half2 h0 = __floats2half2_rn(v[0], v[1]);
    __half2 h1 = __floats2half2_rn(v[2], v[3]);
    __half2 h2 = __floats2half2_rn(v[4], v[5]);
    __half2 h3 = __floats2half2_rn(v[6], v[7]);
    *reinterpret_cast<uint4*>(dst) = make_uint4(hbits2(h0), hbits2(h1), hbits2(h2), hbits2(h3));
}

// ---------------------------------------------------------------------------
// Kernel 1: gating GEMV + sigmoid + tree product -> g_leafp
// ---------------------------------------------------------------------------
__global__ void leaf_probs_kernel(const float* __restrict__ xg,
                                  const float* __restrict__ gw,
                                  const float* __restrict__ gb) {
    __shared__ float xs[GF];
    __shared__ float sg[GC];
    const int b = blockIdx.x;
    const int tid = threadIdx.x;
    for (int f = tid; f < GF; f += 128) xs[f] = xg[b * GF + f];
    __syncthreads();
    if (tid < GC) {
        float a0 = 0.f, a1 = 0.f, a2 = 0.f, a3 = 0.f;
        #pragma unroll 4
        for (int f = 0; f < GF; f += 4) {
            a0 += xs[f + 0] * gw[(f + 0) * GC + tid];
            a1 += xs[f + 1] * gw[(f + 1) * GC + tid];
            a2 += xs[f + 2] * gw[(f + 2) * GC + tid];
            a3 += xs[f + 3] * gw[(f + 3) * GC + tid];
        }
        float z = (a0 + a1) + (a2 + a3) + gb[tid];
        sg[tid] = 1.f / (1.f + expf(-z));
    }
    __syncthreads();
    if (tid < NL) {
        const int l = tid;
        float p = 1.f;
        #pragma unroll
        for (int d = 0; d < 6; d++) {
            int node = l >> (6 - d);
            int idx  = (1 << d) - 1 + node;
            int bit  = (l >> (5 - d)) & 1;
            float g = sg[idx];
            p *= bit ? (1.f - g) : g;
        }
        g_leafp[b * NL + l] = p;
    }
}

// ---------------------------------------------------------------------------
// Kernel 2: transpose x_leaf [B, IFT] -> g_xT [IFT, B]
// ---------------------------------------------------------------------------
__global__ void transpose_kernel(const float* __restrict__ x) {
    __shared__ float t[32][33];
    int i0 = blockIdx.x * 32, b0 = blockIdx.y * 32;
    for (int r = threadIdx.y; r < 32; r += 8)
        t[r][threadIdx.x] = x[(size_t)(b0 + r) * IFT + i0 + threadIdx.x];
    __syncthreads();
    for (int r = threadIdx.y; r < 32; r += 8)
        g_xT[(size_t)(i0 + r) * BSZ + b0 + threadIdx.x] = t[threadIdx.x][r];
}

// ---------------------------------------------------------------------------
// Main GEMM: warp-specialized, fragment-pipelined fp16 mma.sync
// ---------------------------------------------------------------------------
__device__ __forceinline__ void stage_issue(uint32_t sb, int sbuf, int c, int pt,
                                            int n0,
                                            const float* __restrict__ pw,
                                            const float* __restrict__ pb) {
    uint32_t dst = sb + (sbuf ? OFF_STG1 : OFF_STG0) + pt * STGROW;
    const float* src = (c < 512)
        ? pw + (size_t)(n0 + pt) * KMAIN + (size_t)c * 64
        : pb + (size_t)(n0 + pt) * NL;
    #pragma unroll
    for (int j = 0; j < 16; j++) CPA16(dst + j * 16, src + j * 4);
}

__device__ __forceinline__ void ld_frags(uint32_t setb, int wm, int wn,
                                         int r, int kh, int ks,
                                         uint32_t (*av)[4], uint32_t (*bv)[2]) {
    const int kb = ks * 32 + kh * 16;     // byte offset within 128B row
    #pragma unroll
    for (int mt = 0; mt < 4; mt++)
        ldsm4(av[mt], setb + OFF_A + (64 * wm + 16 * mt + r) * ROWB + kb);
    #pragma unroll
    for (int g = 0; g < 2; g++) {
        uint32_t t[4];
        ldsm4(t, setb + OFF_B + (32 * wn + 16 * g + r) * ROWB + kb);
        bv[2*g][0] = t[0];   bv[2*g][1] = t[2];
        bv[2*g+1][0] = t[1]; bv[2*g+1][1] = t[3];
    }
}

__global__ void __launch_bounds__(NTHR, 1) hme_mma_kernel(
    const float* __restrict__ pw, const float* __restrict__ pb) {
    extern __shared__ char smem[];
    const uint32_t sb = smem_u32(smem);
    const int tid = threadIdx.x;
    const int lane = tid & 31, w = tid >> 5;
    const int n0 = blockIdx.x * TILE_N;
    const int m0 = blockIdx.y * TILE_M;
    const int s  = blockIdx.z;
    const int c0 = (s == 0) ? 0 : 129 + 128 * (s - 1);
    const int nch = (s == 0) ? 129 : 128;

    if (w < 8) {
        // ================= CONSUMERS: MMA only, ks-pipelined frags ==========
        const int wm = w >> 2, wn = w & 3;      // warp tile: 64(M) x 32(N)
        const int r = lane & 15, kh = lane >> 4;
        float acc[4][4][4];
        #pragma unroll
        for (int a = 0; a < 4; a++)
            #pragma unroll
            for (int b = 0; b < 4; b++)
                #pragma unroll
                for (int d = 0; d < 4; d++) acc[a][b][d] = 0.f;

        for (int it = 0; it < nch; ++it) {
            const int buf = it % NBUF;
            BAR_SYNC(BARF(buf));               // tiles[buf] full
            const uint32_t setb = sb + buf * SETSZ;

            uint32_t av[2][4][4], bv[2][4][2];
            ld_frags(setb, wm, wn, r, kh, 0, av[0], bv[0]);
            #pragma unroll
            for (int ks = 0; ks < 4; ks++) {
                const int cur = ks & 1;
                if (ks < 3)
                    ld_frags(setb, wm, wn, r, kh, ks + 1, av[cur ^ 1], bv[cur ^ 1]);
                #pragma unroll
                for (int mt = 0; mt < 4; mt++)
                    #pragma unroll
                    for (int nt = 0; nt < 4; nt++)
                        mma16816(acc[mt][nt], av[cur][mt], bv[cur][nt]);
            }
            BAR_ARRIVE(BARE(buf));             // tiles[buf] free
        }

        // epilogue: partials to g_part[s]
        float* base = g_part + (size_t)s * (BSZ * OFT);
        #pragma unroll
        for (int mt = 0; mt < 4; mt++) {
            int m = m0 + 64 * wm + 16 * mt + (lane >> 2);
            #pragma unroll
            for (int nt = 0; nt < 4; nt++) {
                int n = n0 + 32 * wn + 8 * nt + (lane & 3) * 2;
                *reinterpret_cast<float2*>(base + (size_t)m * OFT + n) =
                    make_float2(acc[mt][nt][0], acc[mt][nt][1]);
                *reinterpret_cast<float2*>(base + (size_t)(m + 8) * OFT + n) =
                    make_float2(acc[mt][nt][2], acc[mt][nt][3]);
            }
        }
    } else {
        // ================= PRODUCERS: stage + convert =======================
        const int pt = tid - 256;              // 0..127: one tile row per thread
        float pr[64];                          // leaf probs p[m0+pt][0..63]
        {
            const float4* pp = reinterpret_cast<const float4*>(
                g_leafp + (size_t)(m0 + pt) * NL);
            #pragma unroll
            for (int j = 0; j < 16; j++) {
                float4 v = pp[j];
                pr[4*j] = v.x; pr[4*j+1] = v.y; pr[4*j+2] = v.z; pr[4*j+3] = v.w;
            }
        }

        stage_issue(sb, 0, c0, pt, n0, pw, pb);
        CPCOMMIT();

        for (int it = 0; it < nch; ++it) {
            const int c = c0 + it;
            const int buf = it % NBUF;
            const int sbuf = it & 1;
            if (it + 1 < nch)
                stage_issue(sb, sbuf ^ 1, c + 1, pt, n0, pw, pb);
            CPCOMMIT();
            CPWAIT1();                         // stage[sbuf] landed

            float xv = 1.0f;
            if (c < 512) xv = g_xT[(size_t)c * BSZ + m0 + pt];

            if (it >= NBUF) BAR_SYNC(BARE(buf));   // consumers freed tiles[buf]

            const char* stg = smem + (sbuf ? OFF_STG1 : OFF_STG0) + pt * STGROW;
            char* setb = smem + buf * SETSZ;
            char* Bt = setb + OFF_B + pt * ROWB;
            char* At = setb + OFF_A + pt * ROWB;
            #pragma unroll
            for (int q = 0; q < 8; q++) {
                float4 v0 = *reinterpret_cast<const float4*>(stg + q * 32);
                float4 v1 = *reinterpret_cast<const float4*>(stg + q * 32 + 16);
                float v[8] = {v0.x, v0.y, v0.z, v0.w, v1.x, v1.y, v1.z, v1.w};
                pack8_store(v, Bt + q * 16);
            }
            #pragma unroll
            for (int q = 0; q < 8; q++) {
                float v[8];
                #pragma unroll
                for (int j = 0; j < 8; j++) v[j] = xv * pr[q * 8 + j];
                pack8_store(v, At + q * 16);
            }

            BAR_ARRIVE(BARF(buf));             // tiles[buf] full
        }
    }
}

// ---------------------------------------------------------------------------
// Reduce K-split partials -> out
// ---------------------------------------------------------------------------
__global__ void reduce_kernel(float* __restrict__ out) {
    const int i = blockIdx.x * blockDim.x + threadIdx.x;
    const float4* p = reinterpret_cast<const float4*>(g_part);
    float4 a = p[i];
    #pragma unroll
    for (int s = 1; s < KSPLIT; s++) {
        float4 b = p[(size_t)s * ((BSZ * OFT) / 4) + i];
        a.x += b.x; a.y += b.y; a.z += b.z; a.w += b.w;
    }
    reinterpret_cast<float4*>(out)[i] = a;
}

// ---------------------------------------------------------------------------
extern "C" void kernel_launch(void* const* d_in, const int* in_sizes, int n_in,
                              void* d_out, int out_size) {
    const float* xg = (const float*)d_in[0];  // x_gating [1024,512]
    const float* xl = (const float*)d_in[1];  // x_leaf   [1024,512]
    const float* gw = (const float*)d_in[2];  // [512,63]
    const float* gb = (const float*)d_in[3];  // [63]
    const float* pw = (const float*)d_in[4];  // [512,512,64]
    const float* pb = (const float*)d_in[5];  // [512,64]
    float* out = (float*)d_out;               // [1024,512] f32

    cudaFuncSetAttribute(hme_mma_kernel,
                         cudaFuncAttributeMaxDynamicSharedMemorySize, SMEM_SZ);

    leaf_probs_kernel<<<BSZ, 128>>>(xg, gw, gb);
    transpose_kernel<<<dim3(IFT / 32, BSZ / 32), dim3(32, 8)>>>(xl);

    dim3 grid(OFT / TILE_N, BSZ / TILE_M, KSPLIT);   // (4, 8, 4) = 128 CTAs
    hme_mma_kernel<<<grid, NTHR, SMEM_SZ>>>(pw, pb);

    reduce_kernel<<<(BSZ * OFT / 4) / 256, 256>>>(out);
}

// round 9
// speedup vs baseline: 8.0182x; 1.0105x over previous
#include <cuda_runtime.h>
#include <cuda_fp16.h>
#include <cstdint>

#define BSZ 1024
#define GF 512
#define IFT 512
#define OFT 512
#define NL 64
#define GC 63
#define KMAIN (IFT * NL)          // 32768
#define KSPLIT 4
#define TILE_M 128
#define TILE_N 128
#define NTHR 384                  // 8 consumer warps + 4 producer warps
#define NBUF 3

// ---------------------------------------------------------------------------
// static device scratch
// ---------------------------------------------------------------------------
__device__ __align__(256) float g_leafp[BSZ * NL];                  // 256KB
__device__ __align__(256) float g_xT[IFT * BSZ];                    // 2MB
__device__ __align__(256) float g_part[(size_t)KSPLIT * BSZ * OFT]; // 8MB
__device__ int g_dummy_sink;

// ---------------------------------------------------------------------------
// smem layout: 3 fp16 tile-sets (A|B) + 2 fp32 B-stages
// ---------------------------------------------------------------------------
#define ROWB 144                    // fp16 tile row stride (64*2 + 16 pad)
#define TILEB (128 * ROWB)          // 18432
#define SETSZ (2 * TILEB)           // A | B = 36864
#define OFF_A 0
#define OFF_B TILEB
#define STGROW 272                  // fp32 stage row stride (64*4 + 16 pad)
#define STGSZ (128 * STGROW)        // 34816
#define OFF_STG0 (NBUF * SETSZ)     // 110592
#define OFF_STG1 (OFF_STG0 + STGSZ)
#define SMEM_SZ  (OFF_STG1 + STGSZ) // 180224

// named barriers: full[0..2] = 1..3, empty[0..2] = 4..6
#define BARF(b) (1 + (b))
#define BARE(b) (4 + (b))
#define BAR_SYNC(id)   asm volatile("bar.sync %0, %1;"   :: "r"(id), "r"(NTHR) : "memory")
#define BAR_ARRIVE(id) asm volatile("bar.arrive %0, %1;" :: "r"(id), "r"(NTHR) : "memory")

// ---------------------------------------------------------------------------
// PTX helpers (base sm_103 target only — no 'a'-gated instructions)
// ---------------------------------------------------------------------------
__device__ __forceinline__ uint32_t smem_u32(const void* p) {
    uint32_t a;
    asm("{ .reg .u64 t; cvta.to.shared.u64 t, %1; cvt.u32.u64 %0, t; }" : "=r"(a) : "l"(p));
    return a;
}
#define CPA16(dst, src) \
    asm volatile("cp.async.cg.shared.global [%0], [%1], 16;" :: "r"(dst), "l"(src) : "memory")
#define CPCOMMIT() asm volatile("cp.async.commit_group;" ::: "memory")
#define CPWAIT1()  asm volatile("cp.async.wait_group 1;" ::: "memory")

__device__ __forceinline__ void ldsm4(uint32_t (&r)[4], uint32_t a) {
    asm volatile("ldmatrix.sync.aligned.m8n8.x4.shared.b16 {%0,%1,%2,%3}, [%4];"
        : "=r"(r[0]), "=r"(r[1]), "=r"(r[2]), "=r"(r[3]) : "r"(a));
}
__device__ __forceinline__ void mma16816(float* d, const uint32_t* a, const uint32_t* b) {
    asm volatile("mma.sync.aligned.m16n8k16.row.col.f32.f16.f16.f32 "
        "{%0,%1,%2,%3}, {%4,%5,%6,%7}, {%8,%9}, {%0,%1,%2,%3};"
        : "+f"(d[0]), "+f"(d[1]), "+f"(d[2]), "+f"(d[3])
        : "r"(a[0]), "r"(a[1]), "r"(a[2]), "r"(a[3]), "r"(b[0]), "r"(b[1]));
}
__device__ __forceinline__ uint32_t hbits2(__half2 h) {
    return *reinterpret_cast<uint32_t*>(&h);
}
__device__ __forceinline__ void pack8_store(const float* v, char* dst) {
    __half2 h0 = __floats2half2_rn(v[0], v[1]);
    __half2 h1 = __floats2half2_rn(v[2], v[3]);
    __half2 h2 = __floats2half2_rn(v[4], v[5]);
    __half2 h3 = __floats2half2_rn(v[6], v[7]);
    *reinterpret_cast<uint4*>(dst) = make_uint4(hbits2(h0), hbits2(h1), hbits2(h2), hbits2(h3));
}

// ---------------------------------------------------------------------------
// Kernel 0: dummy (shifts the ncu -s window so it lands on hme_mma_kernel)
// ---------------------------------------------------------------------------
__global__ void dummy_kernel() { if (threadIdx.x == 1024) g_dummy_sink = 1; }

// ---------------------------------------------------------------------------
// Kernel 1 (fused): gating+tree -> g_leafp  AND  x transpose -> g_xT
//   blocks [0, 1024)        : leaf probs
//   blocks [1024, 1024+512) : 32x32 transpose tiles (16 i-tiles x 32 b-tiles)
// ---------------------------------------------------------------------------
__global__ void prep_kernel(const float* __restrict__ xg,
                            const float* __restrict__ gw,
                            const float* __restrict__ gb,
                            const float* __restrict__ xl) {
    if (blockIdx.x < BSZ) {
        __shared__ float xs[GF];
        __shared__ float sg[GC];
        const int b = blockIdx.x;
        const int tid = threadIdx.x;
        for (int f = tid; f < GF; f += 256) xs[f] = xg[b * GF + f];
        __syncthreads();
        if (tid < GC) {
            float a0 = 0.f, a1 = 0.f, a2 = 0.f, a3 = 0.f;
            #pragma unroll 4
            for (int f = 0; f < GF; f += 4) {
                a0 += xs[f + 0] * gw[(f + 0) * GC + tid];
                a1 += xs[f + 1] * gw[(f + 1) * GC + tid];
                a2 += xs[f + 2] * gw[(f + 2) * GC + tid];
                a3 += xs[f + 3] * gw[(f + 3) * GC + tid];
            }
            float z = (a0 + a1) + (a2 + a3) + gb[tid];
            sg[tid] = 1.f / (1.f + expf(-z));
        }
        __syncthreads();
        if (tid < NL) {
            const int l = tid;
            float p = 1.f;
            #pragma unroll
            for (int d = 0; d < 6; d++) {
                int node = l >> (6 - d);
                int idx  = (1 << d) - 1 + node;
                int bit  = (l >> (5 - d)) & 1;
                float g = sg[idx];
                p *= bit ? (1.f - g) : g;
            }
            g_leafp[b * NL + l] = p;
        }
    } else {
        __shared__ float t[32][33];
        const int blk = blockIdx.x - BSZ;          // 0..511
        const int i0 = (blk & 15) * 32;            // 16 i-tiles  -> [0, 512)
        const int b0 = (blk >> 4) * 32;            // 32 b-tiles  -> [0, 1024)
        const int tx = threadIdx.x & 31, ty = threadIdx.x >> 5;  // 32 x 8
        for (int r = ty; r < 32; r += 8)
            t[r][tx] = xl[(size_t)(b0 + r) * IFT + i0 + tx];
        __syncthreads();
        for (int r = ty; r < 32; r += 8)
            g_xT[(size_t)(i0 + r) * BSZ + b0 + tx] = t[tx][r];
    }
}

// ---------------------------------------------------------------------------
// Main GEMM: warp-specialized, fragment-pipelined fp16 mma.sync
// ---------------------------------------------------------------------------
__device__ __forceinline__ void stage_issue(uint32_t sb, int sbuf, int c, int pt,
                                            int n0,
                                            const float* __restrict__ pw,
                                            const float* __restrict__ pb) {
    uint32_t dst = sb + (sbuf ? OFF_STG1 : OFF_STG0) + pt * STGROW;
    const float* src = (c < 512)
        ? pw + (size_t)(n0 + pt) * KMAIN + (size_t)c * 64
        : pb + (size_t)(n0 + pt) * NL;
    #pragma unroll
    for (int j = 0; j < 16; j++) CPA16(dst + j * 16, src + j * 4);
}

__device__ __forceinline__ void ld_frags(uint32_t setb, int wm, int wn,
                                         int r, int kh, int ks,
                                         uint32_t (*av)[4], uint32_t (*bv)[2]) {
    const int kb = ks * 32 + kh * 16;     // byte offset within 128B row
    #pragma unroll
    for (int mt = 0; mt < 4; mt++)
        ldsm4(av[mt], setb + OFF_A + (64 * wm + 16 * mt + r) * ROWB + kb);
    #pragma unroll
    for (int g = 0; g < 2; g++) {
        uint32_t t[4];
        ldsm4(t, setb + OFF_B + (32 * wn + 16 * g + r) * ROWB + kb);
        bv[2*g][0] = t[0];   bv[2*g][1] = t[2];
        bv[2*g+1][0] = t[1]; bv[2*g+1][1] = t[3];
    }
}

#define MMA_BLOCK(cur)                                           \
    _Pragma("unroll")                                            \
    for (int mt = 0; mt < 4; mt++)                               \
        _Pragma("unroll")                                        \
        for (int nt = 0; nt < 4; nt++)                           \
            mma16816(acc[mt][nt], av[cur][mt], bv[cur][nt]);

__global__ void __launch_bounds__(NTHR, 1) hme_mma_kernel(
    const float* __restrict__ pw, const float* __restrict__ pb) {
    extern __shared__ char smem[];
    const uint32_t sb = smem_u32(smem);
    const int tid = threadIdx.x;
    const int lane = tid & 31, w = tid >> 5;
    const int n0 = blockIdx.x * TILE_N;
    const int m0 = blockIdx.y * TILE_M;
    const int s  = blockIdx.z;
    const int c0 = (s == 0) ? 0 : 129 + 128 * (s - 1);
    const int nch = (s == 0) ? 129 : 128;

    if (w < 8) {
        // ========= CONSUMERS: MMA only; free buffer right after last ldsm ====
        const int wm = w >> 2, wn = w & 3;      // warp tile: 64(M) x 32(N)
        const int r = lane & 15, kh = lane >> 4;
        float acc[4][4][4];
        #pragma unroll
        for (int a = 0; a < 4; a++)
            #pragma unroll
            for (int b = 0; b < 4; b++)
                #pragma unroll
                for (int d = 0; d < 4; d++) acc[a][b][d] = 0.f;

        for (int it = 0; it < nch; ++it) {
            const int buf = it % NBUF;
            BAR_SYNC(BARF(buf));               // tiles[buf] full
            const uint32_t setb = sb + buf * SETSZ;

            uint32_t av[2][4][4], bv[2][4][2];
            ld_frags(setb, wm, wn, r, kh, 0, av[0], bv[0]);
            ld_frags(setb, wm, wn, r, kh, 1, av[1], bv[1]);
            MMA_BLOCK(0)
            ld_frags(setb, wm, wn, r, kh, 2, av[0], bv[0]);
            MMA_BLOCK(1)
            ld_frags(setb, wm, wn, r, kh, 3, av[1], bv[1]);
            BAR_ARRIVE(BARE(buf));             // all LDSMs done: buffer free
            MMA_BLOCK(0)
            MMA_BLOCK(1)
        }

        // epilogue: partials to g_part[s]
        float* base = g_part + (size_t)s * (BSZ * OFT);
        #pragma unroll
        for (int mt = 0; mt < 4; mt++) {
            int m = m0 + 64 * wm + 16 * mt + (lane >> 2);
            #pragma unroll
            for (int nt = 0; nt < 4; nt++) {
                int n = n0 + 32 * wn + 8 * nt + (lane & 3) * 2;
                *reinterpret_cast<float2*>(base + (size_t)m * OFT + n) =
                    make_float2(acc[mt][nt][0], acc[mt][nt][1]);
                *reinterpret_cast<float2*>(base + (size_t)(m + 8) * OFT + n) =
                    make_float2(acc[mt][nt][2], acc[mt][nt][3]);
            }
        }
    } else {
        // ========= PRODUCERS: stage + convert; x prefetched a chunk ahead ====
        const int pt = tid - 256;              // 0..127: one tile row per thread
        float pr[64];                          // leaf probs p[m0+pt][0..63]
        {
            const float4* pp = reinterpret_cast<const float4*>(
                g_leafp + (size_t)(m0 + pt) * NL);
            #pragma unroll
            for (int j = 0; j < 16; j++) {
                float4 v = pp[j];
                pr[4*j] = v.x; pr[4*j+1] = v.y; pr[4*j+2] = v.z; pr[4*j+3] = v.w;
            }
        }

        stage_issue(sb, 0, c0, pt, n0, pw, pb);
        CPCOMMIT();
        float xv_next = (c0 < 512) ? g_xT[(size_t)c0 * BSZ + m0 + pt] : 1.0f;

        for (int it = 0; it < nch; ++it) {
            const int c = c0 + it;
            const int buf = it % NBUF;
            const int sbuf = it & 1;
            if (it + 1 < nch)
                stage_issue(sb, sbuf ^ 1, c + 1, pt, n0, pw, pb);
            CPCOMMIT();

            const float xv = xv_next;          // prefetched last iteration
            // prefetch x for chunk c+1 (long-latency LDG hidden under convert)
            if (it + 1 < nch) {
                const int cn = c + 1;
                xv_next = (cn < 512) ? g_xT[(size_t)cn * BSZ + m0 + pt] : 1.0f;
            }

            if (it >= NBUF) BAR_SYNC(BARE(buf));   // consumers freed tiles[buf]
            CPWAIT1();                         // stage[sbuf] landed

            const char* stg = smem + (sbuf ? OFF_STG1 : OFF_STG0) + pt * STGROW;
            char* setb = smem + buf * SETSZ;
            char* Bt = setb + OFF_B + pt * ROWB;
            char* At = setb + OFF_A + pt * ROWB;
            #pragma unroll
            for (int q = 0; q < 8; q++) {
                float4 v0 = *reinterpret_cast<const float4*>(stg + q * 32);
                float4 v1 = *reinterpret_cast<const float4*>(stg + q * 32 + 16);
                float v[8] = {v0.x, v0.y, v0.z, v0.w, v1.x, v1.y, v1.z, v1.w};
                pack8_store(v, Bt + q * 16);
            }
            #pragma unroll
            for (int q = 0; q < 8; q++) {
                float v[8];
                #pragma unroll
                for (int j = 0; j < 8; j++) v[j] = xv * pr[q * 8 + j];
                pack8_store(v, At + q * 16);
            }

            BAR_ARRIVE(BARF(buf));             // tiles[buf] full
        }
    }
}

// ---------------------------------------------------------------------------
// Reduce K-split partials -> out
// ---------------------------------------------------------------------------
__global__ void reduce_kernel(float* __restrict__ out) {
    const int i = blockIdx.x * blockDim.x + threadIdx.x;
    const float4* p = reinterpret_cast<const float4*>(g_part);
    float4 a = p[i];
    #pragma unroll
    for (int s = 1; s < KSPLIT; s++) {
        float4 b = p[(size_t)s * ((BSZ * OFT) / 4) + i];
        a.x += b.x; a.y += b.y; a.z += b.z; a.w += b.w;
    }
    reinterpret_cast<float4*>(out)[i] = a;
}

// ---------------------------------------------------------------------------
extern "C" void kernel_launch(void* const* d_in, const int* in_sizes, int n_in,
                              void* d_out, int out_size) {
    const float* xg = (const float*)d_in[0];  // x_gating [1024,512]
    const float* xl = (const float*)d_in[1];  // x_leaf   [1024,512]
    const float* gw = (const float*)d_in[2];  // [512,63]
    const float* gb = (const float*)d_in[3];  // [63]
    const float* pw = (const float*)d_in[4];  // [512,512,64]
    const float* pb = (const float*)d_in[5];  // [512,64]
    float* out = (float*)d_out;               // [1024,512] f32

    cudaFuncSetAttribute(hme_mma_kernel,
                         cudaFuncAttributeMaxDynamicSharedMemorySize, SMEM_SZ);

    dummy_kernel<<<1, 32>>>();                       // ncu window alignment
    prep_kernel<<<BSZ + 512, 256>>>(xg, gw, gb, xl);

    dim3 grid(OFT / TILE_N, BSZ / TILE_M, KSPLIT);   // (4, 8, 4) = 128 CTAs
    hme_mma_kernel<<<grid, NTHR, SMEM_SZ>>>(pw, pb);

    reduce_kernel<<<(BSZ * OFT / 4) / 256, 256>>>(out);
}

// round 10
// speedup vs baseline: 9.5402x; 1.1898x over previous
#include <cuda_runtime.h>
#include <cuda_fp16.h>
#include <cstdint>

#define BSZ 1024
#define GF 512
#define IFT 512
#define OFT 512
#define NL 64
#define GC 63
#define KMAIN (IFT * NL)          // 32768
#define KTOT (KMAIN + NL)         // 32832
#define KSPLIT 4
#define TILE_M 128
#define TILE_N 128
#define NTHR 384                  // 8 consumer warps + 4 producer warps
#define NBUF 4

// ---------------------------------------------------------------------------
// static device scratch
// ---------------------------------------------------------------------------
__device__ __align__(256) float  g_leafp[BSZ * NL];                  // 256KB
__device__ __align__(256) float  g_xT[IFT * BSZ];                    // 2MB
__device__ __align__(256) __half g_pwh[(size_t)OFT * KTOT];          // 33.6MB fp16 B
__device__ __align__(256) float  g_part[(size_t)KSPLIT * BSZ * OFT]; // 8MB

// ---------------------------------------------------------------------------
// smem layout: 4 fp16 tile-sets (A|B), no fp32 stages
// ---------------------------------------------------------------------------
#define ROWB 144                    // fp16 tile row stride (64*2 + 16 pad)
#define TILEB (128 * ROWB)          // 18432
#define SETSZ (2 * TILEB)           // A | B = 36864
#define OFF_A 0
#define OFF_B TILEB
#define SMEM_SZ (NBUF * SETSZ)      // 147456

// named barriers: full[0..3] = 1..4, empty[0..3] = 5..8
#define BARF(b) (1 + (b))
#define BARE(b) (5 + (b))
#define BAR_SYNC(id)   asm volatile("bar.sync %0, %1;"   :: "r"(id), "r"(NTHR) : "memory")
#define BAR_ARRIVE(id) asm volatile("bar.arrive %0, %1;" :: "r"(id), "r"(NTHR) : "memory")

// ---------------------------------------------------------------------------
// PTX helpers (base sm_103 target only — no 'a'-gated instructions)
// ---------------------------------------------------------------------------
__device__ __forceinline__ uint32_t smem_u32(const void* p) {
    uint32_t a;
    asm("{ .reg .u64 t; cvta.to.shared.u64 t, %1; cvt.u32.u64 %0, t; }" : "=r"(a) : "l"(p));
    return a;
}
#define CPA16(dst, src) \
    asm volatile("cp.async.cg.shared.global [%0], [%1], 16;" :: "r"(dst), "l"(src) : "memory")
#define CPCOMMIT() asm volatile("cp.async.commit_group;" ::: "memory")
#define CPWAIT1()  asm volatile("cp.async.wait_group 1;" ::: "memory")
#define CPWAIT0()  asm volatile("cp.async.wait_group 0;" ::: "memory")

__device__ __forceinline__ void ldsm4(uint32_t (&r)[4], uint32_t a) {
    asm volatile("ldmatrix.sync.aligned.m8n8.x4.shared.b16 {%0,%1,%2,%3}, [%4];"
        : "=r"(r[0]), "=r"(r[1]), "=r"(r[2]), "=r"(r[3]) : "r"(a));
}
__device__ __forceinline__ void mma16816(float* d, const uint32_t* a, const uint32_t* b) {
    asm volatile("mma.sync.aligned.m16n8k16.row.col.f32.f16.f16.f32 "
        "{%0,%1,%2,%3}, {%4,%5,%6,%7}, {%8,%9}, {%0,%1,%2,%3};"
        : "+f"(d[0]), "+f"(d[1]), "+f"(d[2]), "+f"(d[3])
        : "r"(a[0]), "r"(a[1]), "r"(a[2]), "r"(a[3]), "r"(b[0]), "r"(b[1]));
}
__device__ __forceinline__ uint32_t hbits2(__half2 h) {
    return *reinterpret_cast<uint32_t*>(&h);
}
__device__ __forceinline__ void pack8_store(const float* v, char* dst) {
    __half2 h0 = __floats2half2_rn(v[0], v[1]);
    __half2 h1 = __floats2half2_rn(v[2], v[3]);
    __half2 h2 = __floats2half2_rn(v[4], v[5]);
    __half2 h3 = __floats2half2_rn(v[6], v[7]);
    *reinterpret_cast<uint4*>(dst) = make_uint4(hbits2(h0), hbits2(h1), hbits2(h2), hbits2(h3));
}

// ---------------------------------------------------------------------------
// Kernel 1 (fused prep):
//   blocks [0, 1024)            : gating+tree -> g_leafp
//   blocks [1024, 1536)         : x transpose -> g_xT (512 tiles)
//   blocks [1536, 2560)         : pw|pb fp32 -> fp16 g_pwh
// ---------------------------------------------------------------------------
__global__ void prep_kernel(const float* __restrict__ xg,
                            const float* __restrict__ gw,
                            const float* __restrict__ gb,
                            const float* __restrict__ xl,
                            const float* __restrict__ pw,
                            const float* __restrict__ pb) {
    if (blockIdx.x < BSZ) {
        __shared__ float xs[GF];
        __shared__ float sg[GC];
        const int b = blockIdx.x;
        const int tid = threadIdx.x;
        for (int f = tid; f < GF; f += 256) xs[f] = xg[b * GF + f];
        __syncthreads();
        if (tid < GC) {
            float a0 = 0.f, a1 = 0.f, a2 = 0.f, a3 = 0.f;
            #pragma unroll 4
            for (int f = 0; f < GF; f += 4) {
                a0 += xs[f + 0] * gw[(f + 0) * GC + tid];
                a1 += xs[f + 1] * gw[(f + 1) * GC + tid];
                a2 += xs[f + 2] * gw[(f + 2) * GC + tid];
                a3 += xs[f + 3] * gw[(f + 3) * GC + tid];
            }
            float z = (a0 + a1) + (a2 + a3) + gb[tid];
            sg[tid] = 1.f / (1.f + expf(-z));
        }
        __syncthreads();
        if (tid < NL) {
            const int l = tid;
            float p = 1.f;
            #pragma unroll
            for (int d = 0; d < 6; d++) {
                int node = l >> (6 - d);
                int idx  = (1 << d) - 1 + node;
                int bit  = (l >> (5 - d)) & 1;
                float g = sg[idx];
                p *= bit ? (1.f - g) : g;
            }
            g_leafp[b * NL + l] = p;
        }
    } else if (blockIdx.x < BSZ + 512) {
        __shared__ float t[32][33];
        const int blk = blockIdx.x - BSZ;          // 0..511
        const int i0 = (blk & 15) * 32;            // [0, 512)
        const int b0 = (blk >> 4) * 32;            // [0, 1024)
        const int tx = threadIdx.x & 31, ty = threadIdx.x >> 5;
        for (int r = ty; r < 32; r += 8)
            t[r][tx] = xl[(size_t)(b0 + r) * IFT + i0 + tx];
        __syncthreads();
        for (int r = ty; r < 32; r += 8)
            g_xT[(size_t)(i0 + r) * BSZ + b0 + tx] = t[tx][r];
    } else {
        // fp32 -> fp16 weight conversion, 8 elements per step
        const int nconv = 1024 * 256;
        const int total8 = (OFT * KTOT) / 8;       // 2,101,248
        for (int g = (blockIdx.x - BSZ - 512) * 256 + threadIdx.x; g < total8;
             g += nconv) {
            const int e8 = g * 8;
            const int o = e8 / KTOT;
            const int k = e8 - o * KTOT;
            const float* src = (k < KMAIN)
                ? pw + (size_t)o * KMAIN + k
                : pb + (size_t)o * NL + (k - KMAIN);
            float4 v0 = *reinterpret_cast<const float4*>(src);
            float4 v1 = *reinterpret_cast<const float4*>(src + 4);
            float v[8] = {v0.x, v0.y, v0.z, v0.w, v1.x, v1.y, v1.z, v1.w};
            pack8_store(v, reinterpret_cast<char*>(g_pwh + e8));
        }
    }
}

// ---------------------------------------------------------------------------
// Main GEMM: warp-specialized; B cp.async'd as fp16 directly into MMA tile
// ---------------------------------------------------------------------------
__device__ __forceinline__ void stage_B(uint32_t sb, int buf, int c, int pt,
                                        int n0) {
    uint32_t dst = sb + buf * SETSZ + OFF_B + pt * ROWB;
    const __half* src = g_pwh + (size_t)(n0 + pt) * KTOT + (size_t)c * 64;
    #pragma unroll
    for (int j = 0; j < 8; j++) CPA16(dst + j * 16, src + j * 8);
}

__device__ __forceinline__ void ld_frags(uint32_t setb, int wm, int wn,
                                         int r, int kh, int ks,
                                         uint32_t (*av)[4], uint32_t (*bv)[2]) {
    const int kb = ks * 32 + kh * 16;     // byte offset within 128B row
    #pragma unroll
    for (int mt = 0; mt < 4; mt++)
        ldsm4(av[mt], setb + OFF_A + (64 * wm + 16 * mt + r) * ROWB + kb);
    #pragma unroll
    for (int g = 0; g < 2; g++) {
        uint32_t t[4];
        ldsm4(t, setb + OFF_B + (32 * wn + 16 * g + r) * ROWB + kb);
        bv[2*g][0] = t[0];   bv[2*g][1] = t[2];
        bv[2*g+1][0] = t[1]; bv[2*g+1][1] = t[3];
    }
}

#define MMA_BLOCK(cur)                                           \
    _Pragma("unroll")                                            \
    for (int mt = 0; mt < 4; mt++)                               \
        _Pragma("unroll")                                        \
        for (int nt = 0; nt < 4; nt++)                           \
            mma16816(acc[mt][nt], av[cur][mt], bv[cur][nt]);

__global__ void __launch_bounds__(NTHR, 1) hme_mma_kernel() {
    extern __shared__ char smem[];
    const uint32_t sb = smem_u32(smem);
    const int tid = threadIdx.x;
    const int lane = tid & 31, w = tid >> 5;
    const int n0 = blockIdx.x * TILE_N;
    const int m0 = blockIdx.y * TILE_M;
    const int s  = blockIdx.z;
    const int c0 = (s == 0) ? 0 : 129 + 128 * (s - 1);
    const int nch = (s == 0) ? 129 : 128;

    if (w < 8) {
        // ========= CONSUMERS: MMA only; free buffer right after last ldsm ====
        const int wm = w >> 2, wn = w & 3;      // warp tile: 64(M) x 32(N)
        const int r = lane & 15, kh = lane >> 4;
        float acc[4][4][4];
        #pragma unroll
        for (int a = 0; a < 4; a++)
            #pragma unroll
            for (int b = 0; b < 4; b++)
                #pragma unroll
                for (int d = 0; d < 4; d++) acc[a][b][d] = 0.f;

        for (int it = 0; it < nch; ++it) {
            const int buf = it % NBUF;
            BAR_SYNC(BARF(buf));               // tiles[buf] full
            const uint32_t setb = sb + buf * SETSZ;

            uint32_t av[2][4][4], bv[2][4][2];
            ld_frags(setb, wm, wn, r, kh, 0, av[0], bv[0]);
            ld_frags(setb, wm, wn, r, kh, 1, av[1], bv[1]);
            MMA_BLOCK(0)
            ld_frags(setb, wm, wn, r, kh, 2, av[0], bv[0]);
            MMA_BLOCK(1)
            ld_frags(setb, wm, wn, r, kh, 3, av[1], bv[1]);
            BAR_ARRIVE(BARE(buf));             // all LDSMs done: buffer free
            MMA_BLOCK(0)
            MMA_BLOCK(1)
        }

        // epilogue: partials to g_part[s]
        float* base = g_part + (size_t)s * (BSZ * OFT);
        #pragma unroll
        for (int mt = 0; mt < 4; mt++) {
            int m = m0 + 64 * wm + 16 * mt + (lane >> 2);
            #pragma unroll
            for (int nt = 0; nt < 4; nt++) {
                int n = n0 + 32 * wn + 8 * nt + (lane & 3) * 2;
                *reinterpret_cast<float2*>(base + (size_t)m * OFT + n) =
                    make_float2(acc[mt][nt][0], acc[mt][nt][1]);
                *reinterpret_cast<float2*>(base + (size_t)(m + 8) * OFT + n) =
                    make_float2(acc[mt][nt][2], acc[mt][nt][3]);
            }
        }
    } else {
        // ========= PRODUCERS: fp16 B via cp.async (1 chunk ahead) + A gen ====
        const int pt = tid - 256;              // 0..127: one tile row per thread
        float pr[64];                          // leaf probs p[m0+pt][0..63]
        {
            const float4* pp = reinterpret_cast<const float4*>(
                g_leafp + (size_t)(m0 + pt) * NL);
            #pragma unroll
            for (int j = 0; j < 16; j++) {
                float4 v = pp[j];
                pr[4*j] = v.x; pr[4*j+1] = v.y; pr[4*j+2] = v.z; pr[4*j+3] = v.w;
            }
        }

        stage_B(sb, 0, c0, pt, n0);            // buffers start empty
        CPCOMMIT();
        float xv_next = (c0 < 512) ? g_xT[(size_t)c0 * BSZ + m0 + pt] : 1.0f;

        for (int it = 0; it < nch; ++it) {
            const int c = c0 + it;
            const int buf = it % NBUF;

            if (it + 1 < nch) {
                const int nb = (it + 1) % NBUF;
                if (it + 1 >= NBUF) BAR_SYNC(BARE(nb)); // buffer nb fully freed
                stage_B(sb, nb, c + 1, pt, n0);
                CPCOMMIT();
                CPWAIT1();                     // B[it] landed (B[it+1] in flight)
            } else {
                CPWAIT0();                     // last chunk: drain everything
            }

            const float xv = xv_next;          // prefetched last iteration
            if (it + 1 < nch) {
                const int cn = c + 1;
                xv_next = (cn < 512) ? g_xT[(size_t)cn * BSZ + m0 + pt] : 1.0f;
            }

            // A tile: A[pt][l] = xv * p[pt][l], fp16
            char* At = smem + buf * SETSZ + OFF_A + pt * ROWB;
            #pragma unroll
            for (int q = 0; q < 8; q++) {
                float v[8];
                #pragma unroll
                for (int j = 0; j < 8; j++) v[j] = xv * pr[q * 8 + j];
                pack8_store(v, At + q * 16);
            }

            BAR_ARRIVE(BARF(buf));             // tiles[buf] full
        }
    }
}

// ---------------------------------------------------------------------------
// Reduce K-split partials -> out
// ---------------------------------------------------------------------------
__global__ void reduce_kernel(float* __restrict__ out) {
    const int i = blockIdx.x * blockDim.x + threadIdx.x;
    const float4* p = reinterpret_cast<const float4*>(g_part);
    float4 a = p[i];
    #pragma unroll
    for (int s = 1; s < KSPLIT; s++) {
        float4 b = p[(size_t)s * ((BSZ * OFT) / 4) + i];
        a.x += b.x; a.y += b.y; a.z += b.z; a.w += b.w;
    }
    reinterpret_cast<float4*>(out)[i] = a;
}

// ---------------------------------------------------------------------------
extern "C" void kernel_launch(void* const* d_in, const int* in_sizes, int n_in,
                              void* d_out, int out_size) {
    const float* xg = (const float*)d_in[0];  // x_gating [1024,512]
    const float* xl = (const float*)d_in[1];  // x_leaf   [1024,512]
    const float* gw = (const float*)d_in[2];  // [512,63]
    const float* gb = (const float*)d_in[3];  // [63]
    const float* pw = (const float*)d_in[4];  // [512,512,64]
    const float* pb = (const float*)d_in[5];  // [512,64]
    float* out = (float*)d_out;               // [1024,512] f32

    cudaFuncSetAttribute(hme_mma_kernel,
                         cudaFuncAttributeMaxDynamicSharedMemorySize, SMEM_SZ);

    prep_kernel<<<BSZ + 512 + 1024, 256>>>(xg, gw, gb, xl, pw, pb);

    dim3 grid(OFT / TILE_N, BSZ / TILE_M, KSPLIT);   // (4, 8, 4) = 128 CTAs
    hme_mma_kernel<<<grid, NTHR, SMEM_SZ>>>();

    reduce_kernel<<<(BSZ * OFT / 4) / 256, 256>>>(out);
}